// round 4
// baseline (speedup 1.0000x reference)
#include <cuda_runtime.h>
#include <cuda_bf16.h>

#define L 32768
#define H 256
#define P 256
#define NC 256
#define CHUNK 128   // L / NC

// ---------------- device scratch (no dynamic allocation allowed) -------------
__device__ float g_Bbar_re[P * H];
__device__ float g_Bbar_im[P * H];
__device__ float g_Cre[H * P];
__device__ float g_Cim[H * P];
__device__ float g_Are[P];
__device__ float g_Aim[P];
__device__ float g_Bu_re[L * P];
__device__ float g_Bu_im[L * P];
__device__ float g_xs_re[L * P];
__device__ float g_xs_im[L * P];
__device__ float g_Mre[NC * P], g_Mim[NC * P];
__device__ float g_bre[NC * P], g_bim[NC * P];
__device__ float g_x0re[NC * P], g_x0im[NC * P];

// ---------------- setup: Lambda_bar, B_bar, deinterleave C -------------------
__global__ void k_setup(const float* __restrict__ Lre, const float* __restrict__ Lim,
                        const float* __restrict__ Bin, const float* __restrict__ logstep) {
    int p = blockIdx.x;
    int h = threadIdx.x;
    float lr = Lre[p], li = Lim[p];
    float dt = expf(logstep[p]);
    float ar = lr * dt, ai = li * dt;
    float e = expf(ar);
    float Abr = e * cosf(ai);
    float Abi = e * sinf(ai);
    if (h == 0) { g_Are[p] = Abr; g_Aim[p] = Abi; }
    // coef = (Lambda_bar - 1) / Lambda
    float nr = Abr - 1.0f, ni = Abi;
    float den = lr * lr + li * li;
    float inv = 1.0f / den;
    float cr = (nr * lr + ni * li) * inv;
    float ci = (ni * lr - nr * li) * inv;
    float b0 = Bin[(p * H + h) * 2 + 0];
    float b1 = Bin[(p * H + h) * 2 + 1];
    g_Bbar_re[p * H + h] = cr * b0 - ci * b1;
    g_Bbar_im[p * H + h] = cr * b1 + ci * b0;
}

__global__ void k_deint_C(const float* __restrict__ Cin) {
    int i = blockIdx.x * blockDim.x + threadIdx.x;
    if (i < H * P) {
        g_Cre[i] = Cin[2 * i];
        g_Cim[i] = Cin[2 * i + 1];
    }
}

// ---------------- GEMM 1: Bu[l,p] = sum_h u[l,h] * Bbar[p,h] (re & im) -------
// NT layout, BM=64 BN=64 BK=16, 256 threads, 4x4 microtile, dual-accumulator.
__global__ __launch_bounds__(256) void k_gemm_bu(const float* __restrict__ u) {
    __shared__ float As[16][68];
    __shared__ float Bre[16][68];
    __shared__ float Bim[16][68];
    int bm = blockIdx.x * 64, bn = blockIdx.y * 64;
    int tid = threadIdx.x;
    int tx = tid & 15, ty = tid >> 4;
    int lr = tid >> 2, lc = (tid & 3) * 4;
    float ar_acc[4][4] = {}, ai_acc[4][4] = {};
    const float* uA = u + (bm + lr) * H + lc;
    const float* bR = g_Bbar_re + (bn + lr) * H + lc;
    const float* bI = g_Bbar_im + (bn + lr) * H + lc;
    for (int k0 = 0; k0 < H; k0 += 16) {
        float4 va = *(const float4*)(uA + k0);
        float4 vr = *(const float4*)(bR + k0);
        float4 vi = *(const float4*)(bI + k0);
        As[lc + 0][lr] = va.x; As[lc + 1][lr] = va.y; As[lc + 2][lr] = va.z; As[lc + 3][lr] = va.w;
        Bre[lc + 0][lr] = vr.x; Bre[lc + 1][lr] = vr.y; Bre[lc + 2][lr] = vr.z; Bre[lc + 3][lr] = vr.w;
        Bim[lc + 0][lr] = vi.x; Bim[lc + 1][lr] = vi.y; Bim[lc + 2][lr] = vi.z; Bim[lc + 3][lr] = vi.w;
        __syncthreads();
#pragma unroll
        for (int k = 0; k < 16; k++) {
            float4 a  = *(const float4*)&As[k][ty * 4];
            float4 r  = *(const float4*)&Bre[k][tx * 4];
            float4 im = *(const float4*)&Bim[k][tx * 4];
            float av[4] = {a.x, a.y, a.z, a.w};
            float rv[4] = {r.x, r.y, r.z, r.w};
            float iv[4] = {im.x, im.y, im.z, im.w};
#pragma unroll
            for (int i = 0; i < 4; i++)
#pragma unroll
                for (int j = 0; j < 4; j++) {
                    ar_acc[i][j] += av[i] * rv[j];
                    ai_acc[i][j] += av[i] * iv[j];
                }
        }
        __syncthreads();
    }
#pragma unroll
    for (int i = 0; i < 4; i++) {
        int row = bm + ty * 4 + i;
        float4 o1 = make_float4(ar_acc[i][0], ar_acc[i][1], ar_acc[i][2], ar_acc[i][3]);
        float4 o2 = make_float4(ai_acc[i][0], ai_acc[i][1], ai_acc[i][2], ai_acc[i][3]);
        *(float4*)&g_Bu_re[row * P + bn + tx * 4] = o1;
        *(float4*)&g_Bu_im[row * P + bn + tx * 4] = o2;
    }
}

// ---------------- scan phase 1: per-chunk affine aggregates ------------------
// x_out = M * x_in + b over a chunk; reset sets M = 0.
__global__ __launch_bounds__(256) void k_scan1(const unsigned int* __restrict__ start) {
    int c = blockIdx.x, p = threadIdx.x;
    int l0 = c * CHUNK;
    float Ar = g_Are[p], Ai = g_Aim[p];
    float Mr = 1.0f, Mi = 0.0f, xr = 0.0f, xi = 0.0f;
#pragma unroll 4
    for (int t = 0; t < CHUNK; t++) {
        int l = l0 + t;
        float br = g_Bu_re[l * P + p];
        float bi = g_Bu_im[l * P + p];
        bool s = (start[l] != 0u);
        float pr = s ? 0.0f : xr, pi = s ? 0.0f : xi;
        float mr = s ? 0.0f : Mr, mi = s ? 0.0f : Mi;
        xr = Ar * pr - Ai * pi + br;
        xi = Ar * pi + Ai * pr + bi;
        float nMr = Ar * mr - Ai * mi;
        float nMi = Ar * mi + Ai * mr;
        Mr = s ? 0.0f : nMr;
        Mi = s ? 0.0f : nMi;
    }
    g_Mre[c * P + p] = Mr; g_Mim[c * P + p] = Mi;
    g_bre[c * P + p] = xr; g_bim[c * P + p] = xi;
}

// ---------------- scan phase 2: serial combine over NC chunks ---------------
__global__ void k_scan2(const float* __restrict__ hidden) {
    int p = threadIdx.x;
    float xr = hidden[p], xi = 0.0f;
    for (int c = 0; c < NC; c++) {
        g_x0re[c * P + p] = xr;
        g_x0im[c * P + p] = xi;
        float Mr = g_Mre[c * P + p], Mi = g_Mim[c * P + p];
        float br = g_bre[c * P + p], bi = g_bim[c * P + p];
        float nr = Mr * xr - Mi * xi + br;
        float ni = Mr * xi + Mi * xr + bi;
        xr = nr; xi = ni;
    }
}

// ---------------- scan phase 3: re-scan with correct prefixes, write xs ------
__global__ __launch_bounds__(256) void k_scan3(const unsigned int* __restrict__ start) {
    int c = blockIdx.x, p = threadIdx.x;
    float Ar = g_Are[p], Ai = g_Aim[p];
    float xr = g_x0re[c * P + p], xi = g_x0im[c * P + p];
    int l0 = c * CHUNK;
#pragma unroll 4
    for (int t = 0; t < CHUNK; t++) {
        int l = l0 + t;
        float br = g_Bu_re[l * P + p];
        float bi = g_Bu_im[l * P + p];
        bool s = (start[l] != 0u);
        float pr = s ? 0.0f : xr, pi = s ? 0.0f : xi;
        xr = Ar * pr - Ai * pi + br;
        xi = Ar * pi + Ai * pr + bi;
        g_xs_re[l * P + p] = xr;
        g_xs_im[l * P + p] = xi;
    }
}

// ---------------- GEMM 2: ys = 2*(xr@Cre^T - xi@Cim^T) + u*D -----------------
__global__ __launch_bounds__(256) void k_gemm_y(const float* __restrict__ u,
                                                const float* __restrict__ D,
                                                float* __restrict__ out) {
    __shared__ float Ars[16][68];
    __shared__ float Ais[16][68];
    __shared__ float Crs[16][68];
    __shared__ float Cis[16][68];
    int bm = blockIdx.x * 64, bn = blockIdx.y * 64;
    int tid = threadIdx.x;
    int tx = tid & 15, ty = tid >> 4;
    int lr = tid >> 2, lc = (tid & 3) * 4;
    float acc[4][4] = {};
    const float* xrp = g_xs_re + (bm + lr) * P + lc;
    const float* xip = g_xs_im + (bm + lr) * P + lc;
    const float* crp = g_Cre + (bn + lr) * P + lc;
    const float* cip = g_Cim + (bn + lr) * P + lc;
    for (int k0 = 0; k0 < P; k0 += 16) {
        float4 v1 = *(const float4*)(xrp + k0);
        float4 v2 = *(const float4*)(xip + k0);
        float4 v3 = *(const float4*)(crp + k0);
        float4 v4 = *(const float4*)(cip + k0);
        Ars[lc + 0][lr] = v1.x; Ars[lc + 1][lr] = v1.y; Ars[lc + 2][lr] = v1.z; Ars[lc + 3][lr] = v1.w;
        Ais[lc + 0][lr] = v2.x; Ais[lc + 1][lr] = v2.y; Ais[lc + 2][lr] = v2.z; Ais[lc + 3][lr] = v2.w;
        Crs[lc + 0][lr] = v3.x; Crs[lc + 1][lr] = v3.y; Crs[lc + 2][lr] = v3.z; Crs[lc + 3][lr] = v3.w;
        Cis[lc + 0][lr] = v4.x; Cis[lc + 1][lr] = v4.y; Cis[lc + 2][lr] = v4.z; Cis[lc + 3][lr] = v4.w;
        __syncthreads();
#pragma unroll
        for (int k = 0; k < 16; k++) {
            float4 a = *(const float4*)&Ars[k][ty * 4];
            float4 b = *(const float4*)&Ais[k][ty * 4];
            float4 c = *(const float4*)&Crs[k][tx * 4];
            float4 d = *(const float4*)&Cis[k][tx * 4];
            float av[4] = {a.x, a.y, a.z, a.w};
            float bv[4] = {b.x, b.y, b.z, b.w};
            float cv[4] = {c.x, c.y, c.z, c.w};
            float dv[4] = {d.x, d.y, d.z, d.w};
#pragma unroll
            for (int i = 0; i < 4; i++)
#pragma unroll
                for (int j = 0; j < 4; j++) {
                    acc[i][j] += av[i] * cv[j];
                    acc[i][j] -= bv[i] * dv[j];
                }
        }
        __syncthreads();
    }
    float4 dv4 = *(const float4*)&D[bn + tx * 4];
#pragma unroll
    for (int i = 0; i < 4; i++) {
        int row = bm + ty * 4 + i;
        float4 u4 = *(const float4*)&u[row * H + bn + tx * 4];
        float4 o;
        o.x = 2.0f * acc[i][0] + u4.x * dv4.x;
        o.y = 2.0f * acc[i][1] + u4.y * dv4.y;
        o.z = 2.0f * acc[i][2] + u4.z * dv4.z;
        o.w = 2.0f * acc[i][3] + u4.w * dv4.w;
        *(float4*)&out[row * H + bn + tx * 4] = o;
    }
}

// ---------------- final state write (format inferred from out_size) ----------
__global__ void k_state(float* __restrict__ out, int fmt) {
    int p = threadIdx.x;
    float re = g_xs_re[(L - 1) * P + p];
    float im = g_xs_im[(L - 1) * P + p];
    if (fmt == 2) {          // complex64 viewed as interleaved float32 pairs
        out[2 * p]     = re;
        out[2 * p + 1] = im;
    } else if (fmt == 1) {   // real part only
        out[p] = re;
    }
}

// ---------------- launcher ---------------------------------------------------
extern "C" void kernel_launch(void* const* d_in, const int* in_sizes, int n_in,
                              void* d_out, int out_size) {
    const float* Lre    = (const float*)d_in[0];
    const float* Lim    = (const float*)d_in[1];
    const float* Bin    = (const float*)d_in[2];
    const float* Cin    = (const float*)d_in[3];
    const float* lstep  = (const float*)d_in[4];
    const float* D      = (const float*)d_in[5];
    const float* hidden = (const float*)d_in[6];
    const float* u      = (const float*)d_in[7];
    const unsigned int* start = (const unsigned int*)d_in[8];
    float* out = (float*)d_out;

    // Infer output layout: [state (complex interleaved | real | absent)] ++ ys(L*H)
    int state_floats = out_size - L * H;
    if (state_floats < 0) state_floats = 0;
    int fmt = (state_floats >= 2 * P) ? 2 : (state_floats >= P ? 1 : 0);
    float* ys = out + state_floats;

    k_setup<<<P, H>>>(Lre, Lim, Bin, lstep);
    k_deint_C<<<(H * P + 255) / 256, 256>>>(Cin);

    dim3 g1(L / 64, P / 64);
    k_gemm_bu<<<g1, 256>>>(u);

    k_scan1<<<NC, P>>>(start);
    k_scan2<<<1, P>>>(hidden);
    k_scan3<<<NC, P>>>(start);

    dim3 g2(L / 64, H / 64);
    k_gemm_y<<<g2, 256>>>(u, D, ys);

    k_state<<<1, P>>>(out, fmt);
}

// round 5
// speedup vs baseline: 1.2484x; 1.2484x over previous
#include <cuda_runtime.h>
#include <cuda_bf16.h>

#define L 32768
#define H 256
#define P 256
#define NC 1024
#define CHUNK 32    // L / NC

#define BM 128
#define BN 64
#define BK 16
#define SST 20      // smem row stride (floats), pad 4 -> conflict-free fragment reads

// ---------------- device scratch (no dynamic allocation allowed) -------------
__device__ unsigned g_Bbar_re[P * H];   // tf32 bits
__device__ unsigned g_Bbar_im[P * H];   // tf32 bits
__device__ unsigned g_Cre[H * P];       // tf32 bits
__device__ unsigned g_Cimn[H * P];      // tf32 bits of (-C_im)
__device__ float g_Are[P];
__device__ float g_Aim[P];
__device__ float g_Bu_re[L * P];
__device__ float g_Bu_im[L * P];
__device__ float g_xs_re[L * P];
__device__ float g_xs_im[L * P];
__device__ float g_Mre[NC * P], g_Mim[NC * P];
__device__ float g_bre[NC * P], g_bim[NC * P];
__device__ float g_x0re[NC * P], g_x0im[NC * P];

__device__ __forceinline__ unsigned f2tf(float x) {
    unsigned r;
    asm("cvt.rna.tf32.f32 %0, %1;" : "=r"(r) : "f"(x));
    return r;
}

__device__ __forceinline__ void mma_tf32(float d[4], const unsigned a[4], const unsigned b[2]) {
    asm volatile(
        "mma.sync.aligned.m16n8k8.row.col.f32.tf32.tf32.f32 "
        "{%0,%1,%2,%3},{%4,%5,%6,%7},{%8,%9},{%0,%1,%2,%3};"
        : "+f"(d[0]), "+f"(d[1]), "+f"(d[2]), "+f"(d[3])
        : "r"(a[0]), "r"(a[1]), "r"(a[2]), "r"(a[3]), "r"(b[0]), "r"(b[1]));
}

// ---------------- setup: Lambda_bar, B_bar (tf32), C deint (tf32) ------------
__global__ void k_setup(const float* __restrict__ Lre, const float* __restrict__ Lim,
                        const float* __restrict__ Bin, const float* __restrict__ logstep) {
    int p = blockIdx.x;
    int h = threadIdx.x;
    float lr = Lre[p], li = Lim[p];
    float dt = expf(logstep[p]);
    float e = expf(lr * dt);
    float Abr = e * cosf(li * dt);
    float Abi = e * sinf(li * dt);
    if (h == 0) { g_Are[p] = Abr; g_Aim[p] = Abi; }
    float nr = Abr - 1.0f, ni = Abi;
    float inv = 1.0f / (lr * lr + li * li);
    float cr = (nr * lr + ni * li) * inv;
    float ci = (ni * lr - nr * li) * inv;
    float b0 = Bin[(p * H + h) * 2 + 0];
    float b1 = Bin[(p * H + h) * 2 + 1];
    g_Bbar_re[p * H + h] = f2tf(cr * b0 - ci * b1);
    g_Bbar_im[p * H + h] = f2tf(cr * b1 + ci * b0);
}

__global__ void k_deint_C(const float* __restrict__ Cin) {
    int i = blockIdx.x * blockDim.x + threadIdx.x;
    if (i < H * P) {
        g_Cre[i]  = f2tf(Cin[2 * i]);
        g_Cimn[i] = f2tf(-Cin[2 * i + 1]);
    }
}

// ---------------- GEMM 1 (TF32 MMA): Bu[l,p] = sum_h u[l,h]*Bbar[p,h] --------
__global__ __launch_bounds__(256) void k_gemm_bu(const float* __restrict__ u) {
    __shared__ unsigned As[BM * SST];
    __shared__ unsigned Br[BN * SST];
    __shared__ unsigned Bi[BN * SST];
    int tid = threadIdx.x, lane = tid & 31, wid = tid >> 5;
    int wm = wid & 3, wn = wid >> 2;            // warp grid 4 x 2
    int gp = lane >> 2, tg = lane & 3;
    int bm = blockIdx.x * BM, bn = blockIdx.y * BN;
    float ar[2][4][4] = {}, ai[2][4][4] = {};

    int arow = tid >> 2;                        // 0..63
    int acol = (tid & 3) * 4;                   // 0,4,8,12
    const float* uA = u + (bm + arow) * H + acol;
    const unsigned* gbr = g_Bbar_re + (bn + arow) * H + acol;
    const unsigned* gbi = g_Bbar_im + (bn + arow) * H + acol;

    for (int k0 = 0; k0 < H; k0 += BK) {
        float4 a1 = *(const float4*)(uA + k0);
        float4 a2 = *(const float4*)(uA + 64 * H + k0);
        uint4  r1 = *(const uint4*)(gbr + k0);
        uint4  i1 = *(const uint4*)(gbi + k0);
        __syncthreads();
        unsigned* pa = &As[arow * SST + acol];
        pa[0] = f2tf(a1.x); pa[1] = f2tf(a1.y); pa[2] = f2tf(a1.z); pa[3] = f2tf(a1.w);
        unsigned* pa2 = &As[(arow + 64) * SST + acol];
        pa2[0] = f2tf(a2.x); pa2[1] = f2tf(a2.y); pa2[2] = f2tf(a2.z); pa2[3] = f2tf(a2.w);
        unsigned* pr = &Br[arow * SST + acol];
        pr[0] = r1.x; pr[1] = r1.y; pr[2] = r1.z; pr[3] = r1.w;
        unsigned* pi = &Bi[arow * SST + acol];
        pi[0] = i1.x; pi[1] = i1.y; pi[2] = i1.z; pi[3] = i1.w;
        __syncthreads();
#pragma unroll
        for (int kk = 0; kk < BK; kk += 8) {
            unsigned af[2][4];
#pragma unroll
            for (int mt = 0; mt < 2; mt++) {
                int r0 = (wm * 32 + mt * 16 + gp) * SST + kk + tg;
                af[mt][0] = As[r0];
                af[mt][1] = As[r0 + 8 * SST];
                af[mt][2] = As[r0 + 4];
                af[mt][3] = As[r0 + 8 * SST + 4];
            }
#pragma unroll
            for (int nt = 0; nt < 4; nt++) {
                int c0 = (wn * 32 + nt * 8 + gp) * SST + kk + tg;
                unsigned bfr[2] = { Br[c0], Br[c0 + 4] };
                unsigned bfi[2] = { Bi[c0], Bi[c0 + 4] };
#pragma unroll
                for (int mt = 0; mt < 2; mt++) {
                    mma_tf32(ar[mt][nt], af[mt], bfr);
                    mma_tf32(ai[mt][nt], af[mt], bfi);
                }
            }
        }
    }
#pragma unroll
    for (int mt = 0; mt < 2; mt++)
#pragma unroll
        for (int nt = 0; nt < 4; nt++) {
            int row = bm + wm * 32 + mt * 16 + gp;
            int col = bn + wn * 32 + nt * 8 + 2 * tg;
            *(float2*)&g_Bu_re[row * P + col]       = make_float2(ar[mt][nt][0], ar[mt][nt][1]);
            *(float2*)&g_Bu_re[(row + 8) * P + col] = make_float2(ar[mt][nt][2], ar[mt][nt][3]);
            *(float2*)&g_Bu_im[row * P + col]       = make_float2(ai[mt][nt][0], ai[mt][nt][1]);
            *(float2*)&g_Bu_im[(row + 8) * P + col] = make_float2(ai[mt][nt][2], ai[mt][nt][3]);
        }
}

// ---------------- scan phase 1: per-chunk affine aggregates ------------------
__global__ __launch_bounds__(256) void k_scan1(const unsigned int* __restrict__ start) {
    int c = blockIdx.x, p = threadIdx.x;
    int l0 = c * CHUNK;
    float Ar = g_Are[p], Ai = g_Aim[p];
    float Mr = 1.0f, Mi = 0.0f, xr = 0.0f, xi = 0.0f;
#pragma unroll 8
    for (int t = 0; t < CHUNK; t++) {
        int l = l0 + t;
        float br = g_Bu_re[l * P + p];
        float bi = g_Bu_im[l * P + p];
        bool s = (start[l] != 0u);
        float pr = s ? 0.0f : xr, pi = s ? 0.0f : xi;
        float mr = s ? 0.0f : Mr, mi = s ? 0.0f : Mi;
        xr = Ar * pr - Ai * pi + br;
        xi = Ar * pi + Ai * pr + bi;
        Mr = Ar * mr - Ai * mi;
        Mi = Ar * mi + Ai * mr;
    }
    g_Mre[c * P + p] = Mr; g_Mim[c * P + p] = Mi;
    g_bre[c * P + p] = xr; g_bim[c * P + p] = xi;
}

// ---------------- scan phase 2: serial combine over NC chunks ---------------
__global__ void k_scan2(const float* __restrict__ hidden) {
    int p = threadIdx.x;
    float xr = hidden[p], xi = 0.0f;
    for (int c = 0; c < NC; c++) {
        g_x0re[c * P + p] = xr;
        g_x0im[c * P + p] = xi;
        float Mr = g_Mre[c * P + p], Mi = g_Mim[c * P + p];
        float br = g_bre[c * P + p], bi = g_bim[c * P + p];
        float nr = Mr * xr - Mi * xi + br;
        float ni = Mr * xi + Mi * xr + bi;
        xr = nr; xi = ni;
    }
}

// ---------------- scan phase 3: re-scan with prefixes, write xs --------------
__global__ __launch_bounds__(256) void k_scan3(const unsigned int* __restrict__ start) {
    int c = blockIdx.x, p = threadIdx.x;
    float Ar = g_Are[p], Ai = g_Aim[p];
    float xr = g_x0re[c * P + p], xi = g_x0im[c * P + p];
    int l0 = c * CHUNK;
#pragma unroll 8
    for (int t = 0; t < CHUNK; t++) {
        int l = l0 + t;
        float br = g_Bu_re[l * P + p];
        float bi = g_Bu_im[l * P + p];
        bool s = (start[l] != 0u);
        float pr = s ? 0.0f : xr, pi = s ? 0.0f : xi;
        xr = Ar * pr - Ai * pi + br;
        xi = Ar * pi + Ai * pr + bi;
        g_xs_re[l * P + p] = xr;
        g_xs_im[l * P + p] = xi;
    }
}

// ---------------- GEMM 2 (TF32 MMA): ys = 2*(xr@Cre^T + xi@(-Cim)^T) + u*D ---
__global__ __launch_bounds__(256) void k_gemm_y(const float* __restrict__ u,
                                                const float* __restrict__ D,
                                                float* __restrict__ out) {
    __shared__ unsigned Axr[BM * SST];
    __shared__ unsigned Axi[BM * SST];
    __shared__ unsigned Cr[BN * SST];
    __shared__ unsigned Ci[BN * SST];
    int tid = threadIdx.x, lane = tid & 31, wid = tid >> 5;
    int wm = wid & 3, wn = wid >> 2;
    int gp = lane >> 2, tg = lane & 3;
    int bm = blockIdx.x * BM, bn = blockIdx.y * BN;
    float acc[2][4][4] = {};

    int arow = tid >> 2;
    int acol = (tid & 3) * 4;
    const float* xrp = g_xs_re + (bm + arow) * P + acol;
    const float* xip = g_xs_im + (bm + arow) * P + acol;
    const unsigned* crp = g_Cre  + (bn + arow) * P + acol;
    const unsigned* cip = g_Cimn + (bn + arow) * P + acol;

    for (int k0 = 0; k0 < P; k0 += BK) {
        float4 a1 = *(const float4*)(xrp + k0);
        float4 a2 = *(const float4*)(xrp + 64 * P + k0);
        float4 b1 = *(const float4*)(xip + k0);
        float4 b2 = *(const float4*)(xip + 64 * P + k0);
        uint4  c1 = *(const uint4*)(crp + k0);
        uint4  c2 = *(const uint4*)(cip + k0);
        __syncthreads();
        unsigned* p0 = &Axr[arow * SST + acol];
        p0[0] = f2tf(a1.x); p0[1] = f2tf(a1.y); p0[2] = f2tf(a1.z); p0[3] = f2tf(a1.w);
        unsigned* p1 = &Axr[(arow + 64) * SST + acol];
        p1[0] = f2tf(a2.x); p1[1] = f2tf(a2.y); p1[2] = f2tf(a2.z); p1[3] = f2tf(a2.w);
        unsigned* p2 = &Axi[arow * SST + acol];
        p2[0] = f2tf(b1.x); p2[1] = f2tf(b1.y); p2[2] = f2tf(b1.z); p2[3] = f2tf(b1.w);
        unsigned* p3 = &Axi[(arow + 64) * SST + acol];
        p3[0] = f2tf(b2.x); p3[1] = f2tf(b2.y); p3[2] = f2tf(b2.z); p3[3] = f2tf(b2.w);
        unsigned* p4 = &Cr[arow * SST + acol];
        p4[0] = c1.x; p4[1] = c1.y; p4[2] = c1.z; p4[3] = c1.w;
        unsigned* p5 = &Ci[arow * SST + acol];
        p5[0] = c2.x; p5[1] = c2.y; p5[2] = c2.z; p5[3] = c2.w;
        __syncthreads();
#pragma unroll
        for (int kk = 0; kk < BK; kk += 8) {
            unsigned afr[2][4], afi[2][4];
#pragma unroll
            for (int mt = 0; mt < 2; mt++) {
                int r0 = (wm * 32 + mt * 16 + gp) * SST + kk + tg;
                afr[mt][0] = Axr[r0];
                afr[mt][1] = Axr[r0 + 8 * SST];
                afr[mt][2] = Axr[r0 + 4];
                afr[mt][3] = Axr[r0 + 8 * SST + 4];
                afi[mt][0] = Axi[r0];
                afi[mt][1] = Axi[r0 + 8 * SST];
                afi[mt][2] = Axi[r0 + 4];
                afi[mt][3] = Axi[r0 + 8 * SST + 4];
            }
#pragma unroll
            for (int nt = 0; nt < 4; nt++) {
                int c0 = (wn * 32 + nt * 8 + gp) * SST + kk + tg;
                unsigned bfr[2] = { Cr[c0], Cr[c0 + 4] };
                unsigned bfi[2] = { Ci[c0], Ci[c0 + 4] };
#pragma unroll
                for (int mt = 0; mt < 2; mt++) {
                    mma_tf32(acc[mt][nt], afr[mt], bfr);
                    mma_tf32(acc[mt][nt], afi[mt], bfi);
                }
            }
        }
    }
#pragma unroll
    for (int mt = 0; mt < 2; mt++)
#pragma unroll
        for (int nt = 0; nt < 4; nt++) {
            int row = bm + wm * 32 + mt * 16 + gp;
            int col = bn + wn * 32 + nt * 8 + 2 * tg;
            float2 dv = *(const float2*)&D[col];
            float2 u0 = *(const float2*)&u[row * H + col];
            float2 u1 = *(const float2*)&u[(row + 8) * H + col];
            float2 o0 = make_float2(2.0f * acc[mt][nt][0] + u0.x * dv.x,
                                    2.0f * acc[mt][nt][1] + u0.y * dv.y);
            float2 o1 = make_float2(2.0f * acc[mt][nt][2] + u1.x * dv.x,
                                    2.0f * acc[mt][nt][3] + u1.y * dv.y);
            *(float2*)&out[row * H + col]       = o0;
            *(float2*)&out[(row + 8) * H + col] = o1;
        }
}

// ---------------- final state write (format inferred from out_size) ----------
__global__ void k_state(float* __restrict__ out, int fmt) {
    int p = threadIdx.x;
    float re = g_xs_re[(L - 1) * P + p];
    float im = g_xs_im[(L - 1) * P + p];
    if (fmt == 2) {
        out[2 * p]     = re;
        out[2 * p + 1] = im;
    } else if (fmt == 1) {
        out[p] = re;
    }
}

// ---------------- launcher ---------------------------------------------------
extern "C" void kernel_launch(void* const* d_in, const int* in_sizes, int n_in,
                              void* d_out, int out_size) {
    const float* Lre    = (const float*)d_in[0];
    const float* Lim    = (const float*)d_in[1];
    const float* Bin    = (const float*)d_in[2];
    const float* Cin    = (const float*)d_in[3];
    const float* lstep  = (const float*)d_in[4];
    const float* D      = (const float*)d_in[5];
    const float* hidden = (const float*)d_in[6];
    const float* u      = (const float*)d_in[7];
    const unsigned int* start = (const unsigned int*)d_in[8];
    float* out = (float*)d_out;

    int state_floats = out_size - L * H;
    if (state_floats < 0) state_floats = 0;
    int fmt = (state_floats >= 2 * P) ? 2 : (state_floats >= P ? 1 : 0);
    float* ys = out + state_floats;

    k_setup<<<P, H>>>(Lre, Lim, Bin, lstep);
    k_deint_C<<<(H * P + 255) / 256, 256>>>(Cin);

    dim3 g1(L / BM, P / BN);
    k_gemm_bu<<<g1, 256>>>(u);

    k_scan1<<<NC, P>>>(start);
    k_scan2<<<1, P>>>(hidden);
    k_scan3<<<NC, P>>>(start);

    dim3 g2(L / BM, H / BN);
    k_gemm_y<<<g2, 256>>>(u, D, ys);

    k_state<<<1, P>>>(out, fmt);
}

// round 7
// speedup vs baseline: 1.4839x; 1.1887x over previous
#include <cuda_runtime.h>
#include <cuda_fp16.h>
#include <cstdint>

#define L 32768
#define H 256
#define P 256
#define NC 1024
#define CHUNK 32    // L / NC

#define SST 20      // smem row stride in uints (16 data + 4 pad) -> conflict-free

// ---------------- device scratch (no dynamic allocation allowed) -------------
__device__ unsigned g_u_h[L * H / 2];        // u as half2 (packed along h)
__device__ unsigned g_Bb_re_h[P * H / 2];    // B_bar re as half2 (along h)
__device__ unsigned g_Bb_im_h[P * H / 2];
__device__ unsigned g_C_re_h[H * P / 2];     // C re as half2 (along p)
__device__ unsigned g_C_imn_h[H * P / 2];    // -C im as half2
__device__ float g_Are[P];
__device__ float g_Aim[P];
__device__ float g_Bu_re[L * P];
__device__ float g_Bu_im[L * P];
__device__ __half g_xs_re_h[L * P];
__device__ __half g_xs_im_h[L * P];
__device__ float g_xlast_re[P], g_xlast_im[P];
__device__ float g_Mre[NC * P], g_Mim[NC * P];
__device__ float g_bre[NC * P], g_bim[NC * P];
__device__ float g_x0re[NC * P], g_x0im[NC * P];

// ---------------- helpers -----------------------------------------------------
__device__ __forceinline__ unsigned packh2(float a, float b) {
    __half2 h = __floats2half2_rn(a, b);
    return *reinterpret_cast<unsigned*>(&h);
}

__device__ __forceinline__ uint32_t s2u(const void* p) {
    uint32_t a;
    asm("{ .reg .u64 t; cvta.to.shared.u64 t, %1; cvt.u32.u64 %0, t; }" : "=r"(a) : "l"(p));
    return a;
}

__device__ __forceinline__ void mma_f16(float d[4], const unsigned a[4], const unsigned b[2]) {
    asm volatile(
        "mma.sync.aligned.m16n8k16.row.col.f32.f16.f16.f32 "
        "{%0,%1,%2,%3},{%4,%5,%6,%7},{%8,%9},{%0,%1,%2,%3};"
        : "+f"(d[0]), "+f"(d[1]), "+f"(d[2]), "+f"(d[3])
        : "r"(a[0]), "r"(a[1]), "r"(a[2]), "r"(a[3]), "r"(b[0]), "r"(b[1]));
}

#define CP16(s, g) \
    asm volatile("cp.async.cg.shared.global [%0], [%1], 16;" :: "r"(s), "l"(g) : "memory")
#define CP_COMMIT() asm volatile("cp.async.commit_group;" ::: "memory")
#define CP_WAIT1() asm volatile("cp.async.wait_group 1;" ::: "memory")
#define CP_WAIT0() asm volatile("cp.async.wait_group 0;" ::: "memory")

// ---------------- setup: Lambda_bar, B_bar (half2), C deint (half2) ----------
__global__ void k_setup(const float* __restrict__ Lre, const float* __restrict__ Lim,
                        const float* __restrict__ Bin, const float* __restrict__ logstep) {
    int p = blockIdx.x;
    int h2 = threadIdx.x;                 // 0..127 -> pair (2*h2, 2*h2+1)
    float lr = Lre[p], li = Lim[p];
    float dt = expf(logstep[p]);
    float e = expf(lr * dt);
    float Abr = e * cosf(li * dt);
    float Abi = e * sinf(li * dt);
    if (h2 == 0) { g_Are[p] = Abr; g_Aim[p] = Abi; }
    float nr = Abr - 1.0f, ni = Abi;
    float inv = 1.0f / (lr * lr + li * li);
    float cr = (nr * lr + ni * li) * inv;
    float ci = (ni * lr - nr * li) * inv;
    int h0 = 2 * h2;
    float b00 = Bin[(p * H + h0) * 2 + 0], b01 = Bin[(p * H + h0) * 2 + 1];
    float b10 = Bin[(p * H + h0 + 1) * 2 + 0], b11 = Bin[(p * H + h0 + 1) * 2 + 1];
    float re0 = cr * b00 - ci * b01, im0 = cr * b01 + ci * b00;
    float re1 = cr * b10 - ci * b11, im1 = cr * b11 + ci * b10;
    g_Bb_re_h[p * (H / 2) + h2] = packh2(re0, re1);
    g_Bb_im_h[p * (H / 2) + h2] = packh2(im0, im1);
}

__global__ void k_deint_C(const float* __restrict__ Cin) {
    int i = blockIdx.x * blockDim.x + threadIdx.x;
    if (i < H * P / 2) {
        float4 v = ((const float4*)Cin)[i];       // elements 2i (re,im), 2i+1 (re,im)
        g_C_re_h[i]  = packh2(v.x, v.z);
        g_C_imn_h[i] = packh2(-v.y, -v.w);
    }
}

__global__ void k_conv_u(const float* __restrict__ u) {
    int i = blockIdx.x * blockDim.x + threadIdx.x;
    if (i < L * H / 2) {
        float2 v = ((const float2*)u)[i];
        g_u_h[i] = packh2(v.x, v.y);
    }
}

// ---------------- GEMM 1 (fp16 mma): Bu[l,p] = sum_h u[l,h]*Bbar[p,h] --------
// BM=128 BN=64 BK=32(half), 256 thr, 8 warps (4x2), warp tile 32x32, re+im acc.
#define G1_A  0
#define G1_BR (128 * SST)
#define G1_BI (192 * SST)
#define G1_STG (256 * SST)             // 5120 uints per stage
#define G1_SMEM (2 * G1_STG * 4)       // 40960 B

__global__ void __launch_bounds__(256) k_gemm_bu() {
    extern __shared__ unsigned sm[];
    const uint32_t sb = s2u(sm);
    const int tid = threadIdx.x, lane = tid & 31, wid = tid >> 5;
    const int gp = lane >> 2, tg = lane & 3;
    const int wm = wid & 3, wn = wid >> 2;
    const int bm = blockIdx.x * 128, bn = blockIdx.y * 64;

    const int lr0 = tid >> 2, lc = (tid & 3) * 4;
    const unsigned* sA0 = g_u_h     + (size_t)(bm + lr0) * (H / 2) + lc;
    const unsigned* sA1 = sA0 + 64 * (H / 2);
    const unsigned* sBr = g_Bb_re_h + (size_t)(bn + lr0) * (H / 2) + lc;
    const unsigned* sBi = g_Bb_im_h + (size_t)(bn + lr0) * (H / 2) + lc;
    const uint32_t dA0 = sb + (G1_A  + lr0 * SST + lc) * 4;
    const uint32_t dA1 = sb + (G1_A  + (lr0 + 64) * SST + lc) * 4;
    const uint32_t dBr = sb + (G1_BR + lr0 * SST + lc) * 4;
    const uint32_t dBi = sb + (G1_BI + lr0 * SST + lc) * 4;

    float ar[2][4][4] = {}, ai[2][4][4] = {};

#define G1_PF(c) do { \
        int k0u = (c) * 16; uint32_t bo = ((c) & 1) * (G1_STG * 4); \
        CP16(dA0 + bo, sA0 + k0u); \
        CP16(dA1 + bo, sA1 + k0u); \
        CP16(dBr + bo, sBr + k0u); \
        CP16(dBi + bo, sBi + k0u); \
        CP_COMMIT(); \
    } while (0)

    G1_PF(0);
#pragma unroll
    for (int c = 0; c < 8; c++) {
        if (c < 7) { G1_PF(c + 1); CP_WAIT1(); } else { CP_WAIT0(); }
        __syncthreads();
        const unsigned* S = sm + (c & 1) * G1_STG;
#pragma unroll
        for (int ko = 0; ko < 16; ko += 8) {
            unsigned af[2][4];
#pragma unroll
            for (int mt = 0; mt < 2; mt++) {
                int r0 = (wm * 32 + mt * 16 + gp) * SST + ko + tg;
                af[mt][0] = S[r0];
                af[mt][1] = S[r0 + 8 * SST];
                af[mt][2] = S[r0 + 4];
                af[mt][3] = S[r0 + 8 * SST + 4];
            }
#pragma unroll
            for (int nt = 0; nt < 4; nt++) {
                int c0 = G1_BR + (wn * 32 + nt * 8 + gp) * SST + ko + tg;
                unsigned br[2] = { S[c0], S[c0 + 4] };
                unsigned bi[2] = { S[c0 + (G1_BI - G1_BR)], S[c0 + (G1_BI - G1_BR) + 4] };
#pragma unroll
                for (int mt = 0; mt < 2; mt++) {
                    mma_f16(ar[mt][nt], af[mt], br);
                    mma_f16(ai[mt][nt], af[mt], bi);
                }
            }
        }
        __syncthreads();
    }
#pragma unroll
    for (int mt = 0; mt < 2; mt++)
#pragma unroll
        for (int nt = 0; nt < 4; nt++) {
            int row = bm + wm * 32 + mt * 16 + gp;
            int col = bn + wn * 32 + nt * 8 + 2 * tg;
            *(float2*)&g_Bu_re[(size_t)row * P + col]       = make_float2(ar[mt][nt][0], ar[mt][nt][1]);
            *(float2*)&g_Bu_re[(size_t)(row + 8) * P + col] = make_float2(ar[mt][nt][2], ar[mt][nt][3]);
            *(float2*)&g_Bu_im[(size_t)row * P + col]       = make_float2(ai[mt][nt][0], ai[mt][nt][1]);
            *(float2*)&g_Bu_im[(size_t)(row + 8) * P + col] = make_float2(ai[mt][nt][2], ai[mt][nt][3]);
        }
}

// ---------------- scan phase 1: per-chunk affine aggregates ------------------
__global__ __launch_bounds__(256) void k_scan1(const unsigned int* __restrict__ start) {
    int c = blockIdx.x, p = threadIdx.x;
    int l0 = c * CHUNK;
    float Ar = g_Are[p], Ai = g_Aim[p];
    float Mr = 1.0f, Mi = 0.0f, xr = 0.0f, xi = 0.0f;
#pragma unroll 8
    for (int t = 0; t < CHUNK; t++) {
        int l = l0 + t;
        float br = g_Bu_re[l * P + p];
        float bi = g_Bu_im[l * P + p];
        bool s = (start[l] != 0u);
        float pr = s ? 0.0f : xr, pi = s ? 0.0f : xi;
        float mr = s ? 0.0f : Mr, mi = s ? 0.0f : Mi;
        xr = Ar * pr - Ai * pi + br;
        xi = Ar * pi + Ai * pr + bi;
        Mr = Ar * mr - Ai * mi;
        Mi = Ar * mi + Ai * mr;
    }
    g_Mre[c * P + p] = Mr; g_Mim[c * P + p] = Mi;
    g_bre[c * P + p] = xr; g_bim[c * P + p] = xi;
}

// ---------------- scan phase 2: serial combine over NC chunks ---------------
__global__ void k_scan2(const float* __restrict__ hidden) {
    int p = threadIdx.x;
    float xr = hidden[p], xi = 0.0f;
    for (int c = 0; c < NC; c++) {
        g_x0re[c * P + p] = xr;
        g_x0im[c * P + p] = xi;
        float Mr = g_Mre[c * P + p], Mi = g_Mim[c * P + p];
        float br = g_bre[c * P + p], bi = g_bim[c * P + p];
        float nr = Mr * xr - Mi * xi + br;
        float ni = Mr * xi + Mi * xr + bi;
        xr = nr; xi = ni;
    }
}

// ---------------- scan phase 3: re-scan with prefixes, write xs (fp16) -------
__global__ __launch_bounds__(256) void k_scan3(const unsigned int* __restrict__ start) {
    int c = blockIdx.x, p = threadIdx.x;
    float Ar = g_Are[p], Ai = g_Aim[p];
    float xr = g_x0re[c * P + p], xi = g_x0im[c * P + p];
    int l0 = c * CHUNK;
#pragma unroll 8
    for (int t = 0; t < CHUNK; t++) {
        int l = l0 + t;
        float br = g_Bu_re[l * P + p];
        float bi = g_Bu_im[l * P + p];
        bool s = (start[l] != 0u);
        float pr = s ? 0.0f : xr, pi = s ? 0.0f : xi;
        xr = Ar * pr - Ai * pi + br;
        xi = Ar * pi + Ai * pr + bi;
        g_xs_re_h[l * P + p] = __float2half_rn(xr);
        g_xs_im_h[l * P + p] = __float2half_rn(xi);
    }
    if (c == NC - 1) {
        g_xlast_re[p] = xr;
        g_xlast_im[p] = xi;
    }
}

// ---------------- GEMM 2 (fp16 mma): ys = 2*(xr@Cre^T + xi@(-Cim)^T) + u*D ---
#define G2_AR 0
#define G2_AI (128 * SST)
#define G2_CR (256 * SST)
#define G2_CI (320 * SST)
#define G2_STG (384 * SST)             // 7680 uints per stage
#define G2_SMEM (2 * G2_STG * 4)       // 61440 B

__global__ void __launch_bounds__(256) k_gemm_y(const float* __restrict__ u,
                                                const float* __restrict__ D,
                                                float* __restrict__ out) {
    extern __shared__ unsigned sm[];
    const uint32_t sb = s2u(sm);
    const int tid = threadIdx.x, lane = tid & 31, wid = tid >> 5;
    const int gp = lane >> 2, tg = lane & 3;
    const int wm = wid & 3, wn = wid >> 2;
    const int bm = blockIdx.x * 128, bn = blockIdx.y * 64;

    const int lr0 = tid >> 2, lc = (tid & 3) * 4;
    const unsigned* sR0 = (const unsigned*)g_xs_re_h + (size_t)(bm + lr0) * (P / 2) + lc;
    const unsigned* sR1 = sR0 + 64 * (P / 2);
    const unsigned* sI0 = (const unsigned*)g_xs_im_h + (size_t)(bm + lr0) * (P / 2) + lc;
    const unsigned* sI1 = sI0 + 64 * (P / 2);
    const unsigned* sCr = g_C_re_h  + (size_t)(bn + lr0) * (P / 2) + lc;
    const unsigned* sCi = g_C_imn_h + (size_t)(bn + lr0) * (P / 2) + lc;
    const uint32_t dR0 = sb + (G2_AR + lr0 * SST + lc) * 4;
    const uint32_t dR1 = sb + (G2_AR + (lr0 + 64) * SST + lc) * 4;
    const uint32_t dI0 = sb + (G2_AI + lr0 * SST + lc) * 4;
    const uint32_t dI1 = sb + (G2_AI + (lr0 + 64) * SST + lc) * 4;
    const uint32_t dCr = sb + (G2_CR + lr0 * SST + lc) * 4;
    const uint32_t dCi = sb + (G2_CI + lr0 * SST + lc) * 4;

    float acc[2][4][4] = {};

#define G2_PF(c) do { \
        int k0u = (c) * 16; uint32_t bo = ((c) & 1) * (G2_STG * 4); \
        CP16(dR0 + bo, sR0 + k0u); \
        CP16(dR1 + bo, sR1 + k0u); \
        CP16(dI0 + bo, sI0 + k0u); \
        CP16(dI1 + bo, sI1 + k0u); \
        CP16(dCr + bo, sCr + k0u); \
        CP16(dCi + bo, sCi + k0u); \
        CP_COMMIT(); \
    } while (0)

    G2_PF(0);
#pragma unroll
    for (int c = 0; c < 8; c++) {
        if (c < 7) { G2_PF(c + 1); CP_WAIT1(); } else { CP_WAIT0(); }
        __syncthreads();
        const unsigned* S = sm + (c & 1) * G2_STG;
#pragma unroll
        for (int ko = 0; ko < 16; ko += 8) {
            unsigned afr[2][4], afi[2][4];
#pragma unroll
            for (int mt = 0; mt < 2; mt++) {
                int r0 = (wm * 32 + mt * 16 + gp) * SST + ko + tg;
                afr[mt][0] = S[r0];
                afr[mt][1] = S[r0 + 8 * SST];
                afr[mt][2] = S[r0 + 4];
                afr[mt][3] = S[r0 + 8 * SST + 4];
                afi[mt][0] = S[G2_AI + r0];
                afi[mt][1] = S[G2_AI + r0 + 8 * SST];
                afi[mt][2] = S[G2_AI + r0 + 4];
                afi[mt][3] = S[G2_AI + r0 + 8 * SST + 4];
            }
#pragma unroll
            for (int nt = 0; nt < 4; nt++) {
                int c0 = G2_CR + (wn * 32 + nt * 8 + gp) * SST + ko + tg;
                unsigned bcr[2] = { S[c0], S[c0 + 4] };
                unsigned bci[2] = { S[c0 + (G2_CI - G2_CR)], S[c0 + (G2_CI - G2_CR) + 4] };
#pragma unroll
                for (int mt = 0; mt < 2; mt++) {
                    mma_f16(acc[mt][nt], afr[mt], bcr);
                    mma_f16(acc[mt][nt], afi[mt], bci);
                }
            }
        }
        __syncthreads();
    }
#pragma unroll
    for (int mt = 0; mt < 2; mt++)
#pragma unroll
        for (int nt = 0; nt < 4; nt++) {
            int row = bm + wm * 32 + mt * 16 + gp;
            int col = bn + wn * 32 + nt * 8 + 2 * tg;
            float2 dv = *(const float2*)&D[col];
            float2 u0 = *(const float2*)&u[(size_t)row * H + col];
            float2 u1 = *(const float2*)&u[(size_t)(row + 8) * H + col];
            float2 o0 = make_float2(2.0f * acc[mt][nt][0] + u0.x * dv.x,
                                    2.0f * acc[mt][nt][1] + u0.y * dv.y);
            float2 o1 = make_float2(2.0f * acc[mt][nt][2] + u1.x * dv.x,
                                    2.0f * acc[mt][nt][3] + u1.y * dv.y);
            *(float2*)&out[(size_t)row * H + col]       = o0;
            *(float2*)&out[(size_t)(row + 8) * H + col] = o1;
        }
}

// ---------------- final state write (format inferred from out_size) ----------
__global__ void k_state(float* __restrict__ out, int fmt) {
    int p = threadIdx.x;
    float re = g_xlast_re[p];
    float im = g_xlast_im[p];
    if (fmt == 2) {
        out[2 * p]     = re;
        out[2 * p + 1] = im;
    } else if (fmt == 1) {
        out[p] = re;
    }
}

// ---------------- launcher ---------------------------------------------------
extern "C" void kernel_launch(void* const* d_in, const int* in_sizes, int n_in,
                              void* d_out, int out_size) {
    const float* Lre    = (const float*)d_in[0];
    const float* Lim    = (const float*)d_in[1];
    const float* Bin    = (const float*)d_in[2];
    const float* Cin    = (const float*)d_in[3];
    const float* lstep  = (const float*)d_in[4];
    const float* D      = (const float*)d_in[5];
    const float* hidden = (const float*)d_in[6];
    const float* u      = (const float*)d_in[7];
    const unsigned int* start = (const unsigned int*)d_in[8];
    float* out = (float*)d_out;

    int state_floats = out_size - L * H;
    if (state_floats < 0) state_floats = 0;
    int fmt = (state_floats >= 2 * P) ? 2 : (state_floats >= P ? 1 : 0);
    float* ys = out + state_floats;

    cudaFuncSetAttribute(k_gemm_bu, cudaFuncAttributeMaxDynamicSharedMemorySize, G1_SMEM);
    cudaFuncSetAttribute(k_gemm_y,  cudaFuncAttributeMaxDynamicSharedMemorySize, G2_SMEM);

    k_setup<<<P, H / 2>>>(Lre, Lim, Bin, lstep);
    k_deint_C<<<(H * P / 2 + 255) / 256, 256>>>(Cin);
    k_conv_u<<<(L * H / 2 + 255) / 256, 256>>>(u);

    dim3 g1(L / 128, P / 64);
    k_gemm_bu<<<g1, 256, G1_SMEM>>>();

    k_scan1<<<NC, P>>>(start);
    k_scan2<<<1, P>>>(hidden);
    k_scan3<<<NC, P>>>(start);

    dim3 g2(L / 128, H / 64);
    k_gemm_y<<<g2, 256, G2_SMEM>>>(u, D, ys);

    k_state<<<1, P>>>(out, fmt);
}

// round 8
// speedup vs baseline: 2.9970x; 2.0197x over previous
#include <cuda_runtime.h>
#include <cuda_fp16.h>
#include <cstdint>

#define L 32768
#define H 256
#define P 256
#define NC 1024
#define CHUNK 32    // L / NC

#define SST 20      // smem row stride in uints (16 data + 4 pad)
#define STG 3840    // (128 + 64) * SST uints per stage

// ---------------- device scratch (no dynamic allocation allowed) -------------
__device__ unsigned g_u_h[L * H / 2];        // u as half2 (packed along h)
__device__ unsigned g_Bcat[512 * (H / 2)];   // rows 0-255: B_bar re; 256-511: im (half2)
__device__ unsigned g_Ccat[H * 256];         // row h: [Cre(128 uints) | -Cim(128)] half2
__device__ float g_Are[P];
__device__ float g_Aim[P];
__device__ float g_Bu[L * 512];              // [l][0:256]=re, [256:512]=im
__device__ unsigned g_xs_h[L * 256];         // half: [l][0:256]=xr, [256:512]=xi
__device__ float g_Mre[NC * P], g_Mim[NC * P];
__device__ float g_bre[NC * P], g_bim[NC * P];
__device__ float g_x0re[NC * P], g_x0im[NC * P];

// ---------------- helpers -----------------------------------------------------
__device__ __forceinline__ unsigned packh2(float a, float b) {
    __half2 h = __floats2half2_rn(a, b);
    return *reinterpret_cast<unsigned*>(&h);
}

__device__ __forceinline__ uint32_t s2u(const void* p) {
    uint32_t a;
    asm("{ .reg .u64 t; cvta.to.shared.u64 t, %1; cvt.u32.u64 %0, t; }" : "=r"(a) : "l"(p));
    return a;
}

__device__ __forceinline__ void mma_f16(float d[4], const unsigned a[4], const unsigned b[2]) {
    asm volatile(
        "mma.sync.aligned.m16n8k16.row.col.f32.f16.f16.f32 "
        "{%0,%1,%2,%3},{%4,%5,%6,%7},{%8,%9},{%0,%1,%2,%3};"
        : "+f"(d[0]), "+f"(d[1]), "+f"(d[2]), "+f"(d[3])
        : "r"(a[0]), "r"(a[1]), "r"(a[2]), "r"(a[3]), "r"(b[0]), "r"(b[1]));
}

__device__ __forceinline__ void ldsm_x4(unsigned r[4], uint32_t addr) {
    asm volatile("ldmatrix.sync.aligned.m8n8.x4.shared.b16 {%0,%1,%2,%3}, [%4];"
        : "=r"(r[0]), "=r"(r[1]), "=r"(r[2]), "=r"(r[3]) : "r"(addr));
}

#define CP16(s, g) \
    asm volatile("cp.async.cg.shared.global [%0], [%1], 16;" :: "r"(s), "l"(g) : "memory")
#define CP_COMMIT() asm volatile("cp.async.commit_group;" ::: "memory")
#define CP_WAIT1() asm volatile("cp.async.wait_group 1;" ::: "memory")
#define CP_WAIT0() asm volatile("cp.async.wait_group 0;" ::: "memory")

// ---------------- setup: Lambda_bar, B_cat (half2), C_cat (half2) ------------
__global__ void k_setup(const float* __restrict__ Lre, const float* __restrict__ Lim,
                        const float* __restrict__ Bin, const float* __restrict__ logstep) {
    int p = blockIdx.x;
    int h2 = threadIdx.x;                 // 0..127 -> pair (2*h2, 2*h2+1)
    float lr = Lre[p], li = Lim[p];
    float dt = expf(logstep[p]);
    float e = expf(lr * dt);
    float Abr = e * cosf(li * dt);
    float Abi = e * sinf(li * dt);
    if (h2 == 0) { g_Are[p] = Abr; g_Aim[p] = Abi; }
    float nr = Abr - 1.0f, ni = Abi;
    float inv = 1.0f / (lr * lr + li * li);
    float cr = (nr * lr + ni * li) * inv;
    float ci = (ni * lr - nr * li) * inv;
    int h0 = 2 * h2;
    float b00 = Bin[(p * H + h0) * 2 + 0], b01 = Bin[(p * H + h0) * 2 + 1];
    float b10 = Bin[(p * H + h0 + 1) * 2 + 0], b11 = Bin[(p * H + h0 + 1) * 2 + 1];
    float re0 = cr * b00 - ci * b01, im0 = cr * b01 + ci * b00;
    float re1 = cr * b10 - ci * b11, im1 = cr * b11 + ci * b10;
    g_Bcat[p * (H / 2) + h2]       = packh2(re0, re1);
    g_Bcat[(P + p) * (H / 2) + h2] = packh2(im0, im1);
}

__global__ void k_deint_C(const float* __restrict__ Cin) {
    int i = blockIdx.x * blockDim.x + threadIdx.x;   // (h, p-pair)
    if (i < H * P / 2) {
        int h = i >> 7, pp = i & 127;
        float4 v = ((const float4*)Cin)[i];
        g_Ccat[h * 256 + pp]       = packh2(v.x, v.z);
        g_Ccat[h * 256 + 128 + pp] = packh2(-v.y, -v.w);
    }
}

__global__ void k_conv_u(const float* __restrict__ u) {
    int i = blockIdx.x * blockDim.x + threadIdx.x;
    if (i < L * H / 2) {
        float2 v = ((const float2*)u)[i];
        g_u_h[i] = packh2(v.x, v.y);
    }
}

// ---------------- unified fp16 GEMM: out[M=128, N=64 tile], K = KH2*2 halves --
// A row-major [m][KH2 uints], B row-major [n][KH2 uints], NT product.
template<int KH2, bool EPI_Y>
__global__ __launch_bounds__(256, 3) void k_gemm(const unsigned* __restrict__ Ag,
                                                 const unsigned* __restrict__ Bg,
                                                 float* __restrict__ Cout, int ldc,
                                                 const float* __restrict__ u,
                                                 const float* __restrict__ Dv) {
    constexpr int KITER = KH2 / 16;
    __shared__ unsigned sm[2 * STG];
    const uint32_t sb = s2u(sm);
    const int tid = threadIdx.x, lane = tid & 31, wid = tid >> 5;
    const int bm = blockIdx.x * 128, bn = blockIdx.y * 64;
    const int wr = (wid & 3) * 32, wc = (wid >> 2) * 32;

    const int lr0 = tid >> 2, lc = (tid & 3) * 4;
    const unsigned* gA0 = Ag + (size_t)(bm + lr0) * KH2 + lc;
    const unsigned* gA1 = gA0 + (size_t)64 * KH2;
    const unsigned* gB  = Bg + (size_t)(bn + lr0) * KH2 + lc;
    const uint32_t dA0 = sb + (lr0 * SST + lc) * 4;
    const uint32_t dA1 = sb + ((lr0 + 64) * SST + lc) * 4;
    const uint32_t dB  = sb + ((128 + lr0) * SST + lc) * 4;

    // ldmatrix per-thread base offsets (bytes)
    const uint32_t aoff = ((wr + (lane & 15)) * SST + ((lane >> 4) << 2)) * 4;
    const int lg = lane >> 3;
    const uint32_t boff = ((128 + wc + (lg & 2) * 4 + (lane & 7)) * SST + ((lg & 1) << 2)) * 4;

    float acc[2][4][4] = {};

#define PF(c) do { int k0 = (c) * 16; uint32_t bo = ((c) & 1) * (STG * 4); \
        CP16(dA0 + bo, gA0 + k0); CP16(dA1 + bo, gA1 + k0); CP16(dB + bo, gB + k0); \
        CP_COMMIT(); } while (0)

    PF(0);
#pragma unroll 1
    for (int c = 0; c < KITER; c++) {
        if (c < KITER - 1) { PF(c + 1); CP_WAIT1(); } else { CP_WAIT0(); }
        __syncthreads();
        const uint32_t Sb = sb + (c & 1) * (STG * 4);
#pragma unroll
        for (int ko = 0; ko < 16; ko += 8) {
            unsigned af[2][4];
            ldsm_x4(af[0], Sb + aoff + ko * 4);
            ldsm_x4(af[1], Sb + aoff + (16 * SST + ko) * 4);
#pragma unroll
            for (int nt2 = 0; nt2 < 2; nt2++) {
                unsigned bf[4];
                ldsm_x4(bf, Sb + boff + (nt2 * 16 * SST + ko) * 4);
#pragma unroll
                for (int mt = 0; mt < 2; mt++) {
                    mma_f16(acc[mt][2 * nt2],     af[mt], bf);
                    mma_f16(acc[mt][2 * nt2 + 1], af[mt], bf + 2);
                }
            }
        }
        __syncthreads();
    }
#undef PF

    const int gp = lane >> 2, tg = lane & 3;
#pragma unroll
    for (int mt = 0; mt < 2; mt++)
#pragma unroll
        for (int nt = 0; nt < 4; nt++) {
            int row = bm + wr + mt * 16 + gp;
            int col = bn + wc + nt * 8 + 2 * tg;
            if (EPI_Y) {
                float2 dv = *(const float2*)&Dv[col];
                float2 u0 = *(const float2*)&u[(size_t)row * H + col];
                float2 u1 = *(const float2*)&u[(size_t)(row + 8) * H + col];
                float2 o0 = make_float2(2.0f * acc[mt][nt][0] + u0.x * dv.x,
                                        2.0f * acc[mt][nt][1] + u0.y * dv.y);
                float2 o1 = make_float2(2.0f * acc[mt][nt][2] + u1.x * dv.x,
                                        2.0f * acc[mt][nt][3] + u1.y * dv.y);
                *(float2*)&Cout[(size_t)row * ldc + col]       = o0;
                *(float2*)&Cout[(size_t)(row + 8) * ldc + col] = o1;
            } else {
                *(float2*)&Cout[(size_t)row * ldc + col] =
                    make_float2(acc[mt][nt][0], acc[mt][nt][1]);
                *(float2*)&Cout[(size_t)(row + 8) * ldc + col] =
                    make_float2(acc[mt][nt][2], acc[mt][nt][3]);
            }
        }
}

// ---------------- scan phase 1: per-chunk affine aggregates ------------------
__global__ __launch_bounds__(256) void k_scan1(const unsigned int* __restrict__ start) {
    int c = blockIdx.x, p = threadIdx.x;
    int l0 = c * CHUNK;
    float Ar = g_Are[p], Ai = g_Aim[p];
    float Mr = 1.0f, Mi = 0.0f, xr = 0.0f, xi = 0.0f;
#pragma unroll 8
    for (int t = 0; t < CHUNK; t++) {
        int l = l0 + t;
        float br = g_Bu[(size_t)l * 512 + p];
        float bi = g_Bu[(size_t)l * 512 + 256 + p];
        bool s = (start[l] != 0u);
        float pr = s ? 0.0f : xr, pi = s ? 0.0f : xi;
        float mr = s ? 0.0f : Mr, mi = s ? 0.0f : Mi;
        xr = Ar * pr - Ai * pi + br;
        xi = Ar * pi + Ai * pr + bi;
        Mr = Ar * mr - Ai * mi;
        Mi = Ar * mi + Ai * mr;
    }
    g_Mre[c * P + p] = Mr; g_Mim[c * P + p] = Mi;
    g_bre[c * P + p] = xr; g_bim[c * P + p] = xi;
}

// ---------------- scan phase 2: parallel combine over NC chunks --------------
// grid 8 blocks (32 p-channels each), 8 warps = 8 c-stripes of 128 chunks.
__global__ __launch_bounds__(256) void k_scan2(const float* __restrict__ hidden) {
    __shared__ float sMr[8][32], sMi[8][32], sbr[8][32], sbi[8][32];
    int lane = threadIdx.x & 31, w = threadIdx.x >> 5;
    int p = blockIdx.x * 32 + lane;
    int c0 = w * (NC / 8);

    // phase 1: per-thread affine composition over 128 chunks
    float Mr = 1.0f, Mi = 0.0f, br = 0.0f, bi = 0.0f;
    for (int j = 0; j < NC / 8; j++) {
        int c = c0 + j;
        float mr = g_Mre[c * P + p], mi = g_Mim[c * P + p];
        float vr = g_bre[c * P + p], vi = g_bim[c * P + p];
        float nMr = mr * Mr - mi * Mi;
        float nMi = mr * Mi + mi * Mr;
        float nbr = mr * br - mi * bi + vr;
        float nbi = mr * bi + mi * br + vi;
        Mr = nMr; Mi = nMi; br = nbr; bi = nbi;
    }
    sMr[w][lane] = Mr; sMi[w][lane] = Mi; sbr[w][lane] = br; sbi[w][lane] = bi;
    __syncthreads();

    // phase 2: warp 0 turns warp totals into exclusive prefixes (per p)
    if (w == 0) {
        float er = 1.0f, ei = 0.0f, fr = 0.0f, fi = 0.0f;
        for (int ww = 0; ww < 8; ww++) {
            float tMr = sMr[ww][lane], tMi = sMi[ww][lane];
            float tbr = sbr[ww][lane], tbi = sbi[ww][lane];
            sMr[ww][lane] = er; sMi[ww][lane] = ei;
            sbr[ww][lane] = fr; sbi[ww][lane] = fi;
            float ner = tMr * er - tMi * ei;
            float nei = tMr * ei + tMi * er;
            float nfr = tMr * fr - tMi * fi + tbr;
            float nfi = tMr * fi + tMi * fr + tbi;
            er = ner; ei = nei; fr = nfr; fi = nfi;
        }
    }
    __syncthreads();

    // phase 3: re-expand within stripe, writing x0 per chunk
    float er = sMr[w][lane], ei = sMi[w][lane];
    float fr = sbr[w][lane], fi = sbi[w][lane];
    float x0r = hidden[p], x0i = 0.0f;
    float xr = er * x0r - ei * x0i + fr;
    float xi = er * x0i + ei * x0r + fi;
    for (int j = 0; j < NC / 8; j++) {
        int c = c0 + j;
        g_x0re[c * P + p] = xr;
        g_x0im[c * P + p] = xi;
        float mr = g_Mre[c * P + p], mi = g_Mim[c * P + p];
        float vr = g_bre[c * P + p], vi = g_bim[c * P + p];
        float nr = mr * xr - mi * xi + vr;
        float ni = mr * xi + mi * xr + vi;
        xr = nr; xi = ni;
    }
}

// ---------------- scan phase 3: re-scan, write xs (half) + final state -------
__global__ __launch_bounds__(256) void k_scan3(const unsigned int* __restrict__ start,
                                               float* __restrict__ out, int fmt) {
    int c = blockIdx.x, p = threadIdx.x;
    float Ar = g_Are[p], Ai = g_Aim[p];
    float xr = g_x0re[c * P + p], xi = g_x0im[c * P + p];
    int l0 = c * CHUNK;
    __half* xs = (__half*)g_xs_h;
#pragma unroll 8
    for (int t = 0; t < CHUNK; t++) {
        int l = l0 + t;
        float br = g_Bu[(size_t)l * 512 + p];
        float bi = g_Bu[(size_t)l * 512 + 256 + p];
        bool s = (start[l] != 0u);
        float pr = s ? 0.0f : xr, pi = s ? 0.0f : xi;
        xr = Ar * pr - Ai * pi + br;
        xi = Ar * pi + Ai * pr + bi;
        xs[(size_t)l * 512 + p]       = __float2half_rn(xr);
        xs[(size_t)l * 512 + 256 + p] = __float2half_rn(xi);
    }
    if (c == NC - 1) {
        if (fmt == 2) { out[2 * p] = xr; out[2 * p + 1] = xi; }
        else if (fmt == 1) { out[p] = xr; }
    }
}

// ---------------- launcher ---------------------------------------------------
extern "C" void kernel_launch(void* const* d_in, const int* in_sizes, int n_in,
                              void* d_out, int out_size) {
    const float* Lre    = (const float*)d_in[0];
    const float* Lim    = (const float*)d_in[1];
    const float* Bin    = (const float*)d_in[2];
    const float* Cin    = (const float*)d_in[3];
    const float* lstep  = (const float*)d_in[4];
    const float* D      = (const float*)d_in[5];
    const float* hidden = (const float*)d_in[6];
    const float* u      = (const float*)d_in[7];
    const unsigned int* start = (const unsigned int*)d_in[8];
    float* out = (float*)d_out;

    int state_floats = out_size - L * H;
    if (state_floats < 0) state_floats = 0;
    int fmt = (state_floats >= 2 * P) ? 2 : (state_floats >= P ? 1 : 0);
    float* ys = out + state_floats;

    k_setup<<<P, H / 2>>>(Lre, Lim, Bin, lstep);
    k_deint_C<<<(H * P / 2 + 255) / 256, 256>>>(Cin);
    k_conv_u<<<(L * H / 2 + 255) / 256, 256>>>(u);

    // GEMM1: Bu[l, 0:512] = u @ [Bre; Bim]^T   (K = 256 halves = 128 uints)
    {
        float* bu = g_Bu;  // device-symbol address resolution via kernel arg
        dim3 g(L / 128, 512 / 64);
        void* bu_dev = nullptr;
        cudaGetSymbolAddress(&bu_dev, g_Bu);
        void* a_dev = nullptr;
        cudaGetSymbolAddress(&a_dev, g_u_h);
        void* b_dev = nullptr;
        cudaGetSymbolAddress(&b_dev, g_Bcat);
        k_gemm<128, false><<<g, 256>>>((const unsigned*)a_dev, (const unsigned*)b_dev,
                                       (float*)bu_dev, 512, nullptr, nullptr);
        (void)bu;
    }

    k_scan1<<<NC, P>>>(start);
    k_scan2<<<8, 256>>>(hidden);
    k_scan3<<<NC, P>>>(start, out, fmt);

    // GEMM2: ys = 2 * (xs_cat @ Ccat^T) + u * D   (K = 512 halves = 256 uints)
    {
        dim3 g(L / 128, H / 64);
        void* a_dev = nullptr;
        cudaGetSymbolAddress(&a_dev, g_xs_h);
        void* b_dev = nullptr;
        cudaGetSymbolAddress(&b_dev, g_Ccat);
        k_gemm<256, true><<<g, 256>>>((const unsigned*)a_dev, (const unsigned*)b_dev,
                                      ys, H, u, D);
    }
}

// round 9
// speedup vs baseline: 3.2899x; 1.0977x over previous
#include <cuda_runtime.h>
#include <cuda_fp16.h>
#include <cstdint>

#define L 32768
#define H 256
#define P 256
#define NC 1024
#define CHUNK 32    // L / NC

#define SST 20      // smem row stride in uints (16 data + 4 pad)
#define STG (256 * SST)   // (128 A rows + 128 B rows) * SST uints per stage

// ---------------- device scratch (no dynamic allocation allowed) -------------
__device__ unsigned g_u_h[L * H / 2];        // u as half2 (packed along h)
__device__ unsigned g_Bcat[512 * (H / 2)];   // rows 0-255: B_bar re; 256-511: im (half2)
__device__ unsigned g_Ccat[H * 256];         // row h: [Cre(128 uints) | -Cim(128)] half2
__device__ float g_Are[P];
__device__ float g_Aim[P];
__device__ __half g_Bu_h[L * 512];           // [l][0:256]=re, [256:512]=im (half)
__device__ unsigned g_xs_h[L * 256];         // half: [l][0:256]=xr, [256:512]=xi
__device__ float g_Mre[NC * P], g_Mim[NC * P];
__device__ float g_bre[NC * P], g_bim[NC * P];
__device__ float g_x0re[NC * P], g_x0im[NC * P];

// ---------------- helpers -----------------------------------------------------
__device__ __forceinline__ unsigned packh2(float a, float b) {
    __half2 h = __floats2half2_rn(a, b);
    return *reinterpret_cast<unsigned*>(&h);
}

__device__ __forceinline__ uint32_t s2u(const void* p) {
    uint32_t a;
    asm("{ .reg .u64 t; cvta.to.shared.u64 t, %1; cvt.u32.u64 %0, t; }" : "=r"(a) : "l"(p));
    return a;
}

__device__ __forceinline__ void mma_f16(float d[4], const unsigned a[4], const unsigned b[2]) {
    asm volatile(
        "mma.sync.aligned.m16n8k16.row.col.f32.f16.f16.f32 "
        "{%0,%1,%2,%3},{%4,%5,%6,%7},{%8,%9},{%0,%1,%2,%3};"
        : "+f"(d[0]), "+f"(d[1]), "+f"(d[2]), "+f"(d[3])
        : "r"(a[0]), "r"(a[1]), "r"(a[2]), "r"(a[3]), "r"(b[0]), "r"(b[1]));
}

__device__ __forceinline__ void ldsm_x4(unsigned r[4], uint32_t addr) {
    asm volatile("ldmatrix.sync.aligned.m8n8.x4.shared.b16 {%0,%1,%2,%3}, [%4];"
        : "=r"(r[0]), "=r"(r[1]), "=r"(r[2]), "=r"(r[3]) : "r"(addr));
}

#define CP16(s, g) \
    asm volatile("cp.async.cg.shared.global [%0], [%1], 16;" :: "r"(s), "l"(g) : "memory")
#define CP_COMMIT() asm volatile("cp.async.commit_group;" ::: "memory")
#define CP_WAIT1() asm volatile("cp.async.wait_group 1;" ::: "memory")
#define CP_WAIT0() asm volatile("cp.async.wait_group 0;" ::: "memory")

// ---------------- setup: Lambda_bar, B_cat (half2), C_cat (half2) ------------
__global__ void k_setup(const float* __restrict__ Lre, const float* __restrict__ Lim,
                        const float* __restrict__ Bin, const float* __restrict__ logstep) {
    int p = blockIdx.x;
    int h2 = threadIdx.x;                 // 0..127 -> pair (2*h2, 2*h2+1)
    float lr = Lre[p], li = Lim[p];
    float dt = expf(logstep[p]);
    float e = expf(lr * dt);
    float Abr = e * cosf(li * dt);
    float Abi = e * sinf(li * dt);
    if (h2 == 0) { g_Are[p] = Abr; g_Aim[p] = Abi; }
    float nr = Abr - 1.0f, ni = Abi;
    float inv = 1.0f / (lr * lr + li * li);
    float cr = (nr * lr + ni * li) * inv;
    float ci = (ni * lr - nr * li) * inv;
    int h0 = 2 * h2;
    float b00 = Bin[(p * H + h0) * 2 + 0], b01 = Bin[(p * H + h0) * 2 + 1];
    float b10 = Bin[(p * H + h0 + 1) * 2 + 0], b11 = Bin[(p * H + h0 + 1) * 2 + 1];
    float re0 = cr * b00 - ci * b01, im0 = cr * b01 + ci * b00;
    float re1 = cr * b10 - ci * b11, im1 = cr * b11 + ci * b10;
    g_Bcat[p * (H / 2) + h2]       = packh2(re0, re1);
    g_Bcat[(P + p) * (H / 2) + h2] = packh2(im0, im1);
}

__global__ void k_deint_C(const float* __restrict__ Cin) {
    int i = blockIdx.x * blockDim.x + threadIdx.x;   // (h, p-pair)
    if (i < H * P / 2) {
        int h = i >> 7, pp = i & 127;
        float4 v = ((const float4*)Cin)[i];
        g_Ccat[h * 256 + pp]       = packh2(v.x, v.z);
        g_Ccat[h * 256 + 128 + pp] = packh2(-v.y, -v.w);
    }
}

__global__ void k_conv_u(const float* __restrict__ u) {
    int i = blockIdx.x * blockDim.x + threadIdx.x;
    if (i < L * H / 2) {
        float2 v = ((const float2*)u)[i];
        g_u_h[i] = packh2(v.x, v.y);
    }
}

// ---------------- unified fp16 GEMM: tile M=128, N=128, K staged 32 halves ----
// A row-major [m][KH2 uints], B row-major [n][KH2 uints], NT product.
// 8 warps as 2 (M) x 4 (N); warp tile 64 x 32.
template<int KH2, bool EPI_Y>
__global__ __launch_bounds__(256, 2) void k_gemm(const unsigned* __restrict__ Ag,
                                                 const unsigned* __restrict__ Bg,
                                                 void* __restrict__ Cout, int ldc,
                                                 const float* __restrict__ u,
                                                 const float* __restrict__ Dv) {
    constexpr int KITER = KH2 / 16;
    __shared__ unsigned sm[2 * STG];
    const uint32_t sb = s2u(sm);
    const int tid = threadIdx.x, lane = tid & 31, wid = tid >> 5;
    const int bm = blockIdx.x * 128, bn = blockIdx.y * 128;
    const int wr = (wid & 1) * 64, wc = (wid >> 1) * 32;

    const int lr0 = tid >> 2, lc = (tid & 3) * 4;
    const unsigned* gA0 = Ag + (size_t)(bm + lr0) * KH2 + lc;
    const unsigned* gA1 = gA0 + (size_t)64 * KH2;
    const unsigned* gB0 = Bg + (size_t)(bn + lr0) * KH2 + lc;
    const unsigned* gB1 = gB0 + (size_t)64 * KH2;
    const uint32_t dA0 = sb + (lr0 * SST + lc) * 4;
    const uint32_t dA1 = sb + ((lr0 + 64) * SST + lc) * 4;
    const uint32_t dB0 = sb + ((128 + lr0) * SST + lc) * 4;
    const uint32_t dB1 = sb + ((192 + lr0) * SST + lc) * 4;

    // ldmatrix per-thread base offsets (bytes)
    const uint32_t aoff = ((wr + (lane & 15)) * SST + ((lane >> 4) << 2)) * 4;
    const int lg = lane >> 3;
    const uint32_t boff = ((128 + wc + (lg & 2) * 4 + (lane & 7)) * SST + ((lg & 1) << 2)) * 4;

    float acc[4][4][4] = {};

#define PF(c) do { int k0 = (c) * 16; uint32_t bo = ((c) & 1) * (STG * 4); \
        CP16(dA0 + bo, gA0 + k0); CP16(dA1 + bo, gA1 + k0); \
        CP16(dB0 + bo, gB0 + k0); CP16(dB1 + bo, gB1 + k0); \
        CP_COMMIT(); } while (0)

    PF(0);
#pragma unroll 1
    for (int c = 0; c < KITER; c++) {
        if (c < KITER - 1) { PF(c + 1); CP_WAIT1(); } else { CP_WAIT0(); }
        __syncthreads();
        const uint32_t Sb = sb + (c & 1) * (STG * 4);
#pragma unroll
        for (int ko = 0; ko < 16; ko += 8) {
            unsigned af[4][4];
#pragma unroll
            for (int mt = 0; mt < 4; mt++)
                ldsm_x4(af[mt], Sb + aoff + (mt * 16 * SST + ko) * 4);
#pragma unroll
            for (int nt2 = 0; nt2 < 2; nt2++) {
                unsigned bf[4];
                ldsm_x4(bf, Sb + boff + (nt2 * 16 * SST + ko) * 4);
#pragma unroll
                for (int mt = 0; mt < 4; mt++) {
                    mma_f16(acc[mt][2 * nt2],     af[mt], bf);
                    mma_f16(acc[mt][2 * nt2 + 1], af[mt], bf + 2);
                }
            }
        }
        __syncthreads();
    }
#undef PF

    const int gp = lane >> 2, tg = lane & 3;
#pragma unroll
    for (int mt = 0; mt < 4; mt++)
#pragma unroll
        for (int nt = 0; nt < 4; nt++) {
            int row = bm + wr + mt * 16 + gp;
            int col = bn + wc + nt * 8 + 2 * tg;
            if (EPI_Y) {
                float* outf = (float*)Cout;
                float2 dv = *(const float2*)&Dv[col];
                float2 u0 = *(const float2*)&u[(size_t)row * H + col];
                float2 u1 = *(const float2*)&u[(size_t)(row + 8) * H + col];
                float2 o0 = make_float2(2.0f * acc[mt][nt][0] + u0.x * dv.x,
                                        2.0f * acc[mt][nt][1] + u0.y * dv.y);
                float2 o1 = make_float2(2.0f * acc[mt][nt][2] + u1.x * dv.x,
                                        2.0f * acc[mt][nt][3] + u1.y * dv.y);
                *(float2*)&outf[(size_t)row * ldc + col]       = o0;
                *(float2*)&outf[(size_t)(row + 8) * ldc + col] = o1;
            } else {
                __half* outh = (__half*)Cout;
                *(__half2*)&outh[(size_t)row * ldc + col] =
                    __floats2half2_rn(acc[mt][nt][0], acc[mt][nt][1]);
                *(__half2*)&outh[(size_t)(row + 8) * ldc + col] =
                    __floats2half2_rn(acc[mt][nt][2], acc[mt][nt][3]);
            }
        }
}

// ---------------- scan phase 1: per-chunk affine aggregates ------------------
__global__ __launch_bounds__(256) void k_scan1(const unsigned int* __restrict__ start) {
    int c = blockIdx.x, p = threadIdx.x;
    int l0 = c * CHUNK;
    float Ar = g_Are[p], Ai = g_Aim[p];
    float Mr = 1.0f, Mi = 0.0f, xr = 0.0f, xi = 0.0f;
#pragma unroll 8
    for (int t = 0; t < CHUNK; t++) {
        int l = l0 + t;
        float br = __half2float(g_Bu_h[(size_t)l * 512 + p]);
        float bi = __half2float(g_Bu_h[(size_t)l * 512 + 256 + p]);
        bool s = (start[l] != 0u);
        float pr = s ? 0.0f : xr, pi = s ? 0.0f : xi;
        float mr = s ? 0.0f : Mr, mi = s ? 0.0f : Mi;
        xr = Ar * pr - Ai * pi + br;
        xi = Ar * pi + Ai * pr + bi;
        Mr = Ar * mr - Ai * mi;
        Mi = Ar * mi + Ai * mr;
    }
    g_Mre[c * P + p] = Mr; g_Mim[c * P + p] = Mi;
    g_bre[c * P + p] = xr; g_bim[c * P + p] = xi;
}

// ---------------- scan phase 2: parallel combine over NC chunks --------------
__global__ __launch_bounds__(256) void k_scan2(const float* __restrict__ hidden) {
    __shared__ float sMr[8][32], sMi[8][32], sbr[8][32], sbi[8][32];
    int lane = threadIdx.x & 31, w = threadIdx.x >> 5;
    int p = blockIdx.x * 32 + lane;
    int c0 = w * (NC / 8);

    float Mr = 1.0f, Mi = 0.0f, br = 0.0f, bi = 0.0f;
    for (int j = 0; j < NC / 8; j++) {
        int c = c0 + j;
        float mr = g_Mre[c * P + p], mi = g_Mim[c * P + p];
        float vr = g_bre[c * P + p], vi = g_bim[c * P + p];
        float nMr = mr * Mr - mi * Mi;
        float nMi = mr * Mi + mi * Mr;
        float nbr = mr * br - mi * bi + vr;
        float nbi = mr * bi + mi * br + vi;
        Mr = nMr; Mi = nMi; br = nbr; bi = nbi;
    }
    sMr[w][lane] = Mr; sMi[w][lane] = Mi; sbr[w][lane] = br; sbi[w][lane] = bi;
    __syncthreads();

    if (w == 0) {
        float er = 1.0f, ei = 0.0f, fr = 0.0f, fi = 0.0f;
        for (int ww = 0; ww < 8; ww++) {
            float tMr = sMr[ww][lane], tMi = sMi[ww][lane];
            float tbr = sbr[ww][lane], tbi = sbi[ww][lane];
            sMr[ww][lane] = er; sMi[ww][lane] = ei;
            sbr[ww][lane] = fr; sbi[ww][lane] = fi;
            float ner = tMr * er - tMi * ei;
            float nei = tMr * ei + tMi * er;
            float nfr = tMr * fr - tMi * fi + tbr;
            float nfi = tMr * fi + tMi * fr + tbi;
            er = ner; ei = nei; fr = nfr; fi = nfi;
        }
    }
    __syncthreads();

    float er = sMr[w][lane], ei = sMi[w][lane];
    float fr = sbr[w][lane], fi = sbi[w][lane];
    float x0r = hidden[p], x0i = 0.0f;
    float xr = er * x0r - ei * x0i + fr;
    float xi = er * x0i + ei * x0r + fi;
    for (int j = 0; j < NC / 8; j++) {
        int c = c0 + j;
        g_x0re[c * P + p] = xr;
        g_x0im[c * P + p] = xi;
        float mr = g_Mre[c * P + p], mi = g_Mim[c * P + p];
        float vr = g_bre[c * P + p], vi = g_bim[c * P + p];
        float nr = mr * xr - mi * xi + vr;
        float ni = mr * xi + mi * xr + vi;
        xr = nr; xi = ni;
    }
}

// ---------------- scan phase 3: re-scan, write xs (half) + final state -------
__global__ __launch_bounds__(256) void k_scan3(const unsigned int* __restrict__ start,
                                               float* __restrict__ out, int fmt) {
    int c = blockIdx.x, p = threadIdx.x;
    float Ar = g_Are[p], Ai = g_Aim[p];
    float xr = g_x0re[c * P + p], xi = g_x0im[c * P + p];
    int l0 = c * CHUNK;
    __half* xs = (__half*)g_xs_h;
#pragma unroll 8
    for (int t = 0; t < CHUNK; t++) {
        int l = l0 + t;
        float br = __half2float(g_Bu_h[(size_t)l * 512 + p]);
        float bi = __half2float(g_Bu_h[(size_t)l * 512 + 256 + p]);
        bool s = (start[l] != 0u);
        float pr = s ? 0.0f : xr, pi = s ? 0.0f : xi;
        xr = Ar * pr - Ai * pi + br;
        xi = Ar * pi + Ai * pr + bi;
        xs[(size_t)l * 512 + p]       = __float2half_rn(xr);
        xs[(size_t)l * 512 + 256 + p] = __float2half_rn(xi);
    }
    if (c == NC - 1) {
        if (fmt == 2) { out[2 * p] = xr; out[2 * p + 1] = xi; }
        else if (fmt == 1) { out[p] = xr; }
    }
}

// ---------------- launcher ---------------------------------------------------
extern "C" void kernel_launch(void* const* d_in, const int* in_sizes, int n_in,
                              void* d_out, int out_size) {
    const float* Lre    = (const float*)d_in[0];
    const float* Lim    = (const float*)d_in[1];
    const float* Bin    = (const float*)d_in[2];
    const float* Cin    = (const float*)d_in[3];
    const float* lstep  = (const float*)d_in[4];
    const float* D      = (const float*)d_in[5];
    const float* hidden = (const float*)d_in[6];
    const float* u      = (const float*)d_in[7];
    const unsigned int* start = (const unsigned int*)d_in[8];
    float* out = (float*)d_out;

    int state_floats = out_size - L * H;
    if (state_floats < 0) state_floats = 0;
    int fmt = (state_floats >= 2 * P) ? 2 : (state_floats >= P ? 1 : 0);
    float* ys = out + state_floats;

    k_setup<<<P, H / 2>>>(Lre, Lim, Bin, lstep);
    k_deint_C<<<(H * P / 2 + 255) / 256, 256>>>(Cin);
    k_conv_u<<<(L * H / 2 + 255) / 256, 256>>>(u);

    // GEMM1: Bu_h[l, 0:512] = u @ [Bre; Bim]^T   (K = 256 halves = 128 uints)
    {
        void *bu_dev = nullptr, *a_dev = nullptr, *b_dev = nullptr;
        cudaGetSymbolAddress(&bu_dev, g_Bu_h);
        cudaGetSymbolAddress(&a_dev, g_u_h);
        cudaGetSymbolAddress(&b_dev, g_Bcat);
        dim3 g(L / 128, 512 / 128);
        k_gemm<128, false><<<g, 256>>>((const unsigned*)a_dev, (const unsigned*)b_dev,
                                       bu_dev, 512, nullptr, nullptr);
    }

    k_scan1<<<NC, P>>>(start);
    k_scan2<<<8, 256>>>(hidden);
    k_scan3<<<NC, P>>>(start, out, fmt);

    // GEMM2: ys = 2 * (xs_cat @ Ccat^T) + u * D   (K = 512 halves = 256 uints)
    {
        void *a_dev = nullptr, *b_dev = nullptr;
        cudaGetSymbolAddress(&a_dev, g_xs_h);
        cudaGetSymbolAddress(&b_dev, g_Ccat);
        dim3 g(L / 128, H / 128);
        k_gemm<256, true><<<g, 256>>>((const unsigned*)a_dev, (const unsigned*)b_dev,
                                      ys, H, u, D);
    }
}

// round 10
// speedup vs baseline: 3.3637x; 1.0224x over previous
#include <cuda_runtime.h>
#include <cuda_fp16.h>
#include <cstdint>

#define L 32768
#define H 256
#define P 256
#define NC 1024
#define CHUNK 32    // L / NC

#define SST 20            // smem row stride in uints (16 data + 4 pad)
#define STG (256 * SST)   // (128 A rows + 128 B rows) * SST uints per stage
#define NSTAGE 3
#define GSMEM (NSTAGE * STG * 4)

// ---------------- device scratch (no dynamic allocation allowed) -------------
__device__ unsigned g_u_h[L * H / 2];        // u as half2 (packed along h)
__device__ unsigned g_Bcat[512 * (H / 2)];   // rows 0-255: B_bar re; 256-511: im (half2)
__device__ unsigned g_Ccat[H * 256];         // row h: [Cre(128 uints) | -Cim(128)] half2
__device__ float g_Are[P];
__device__ float g_Aim[P];
__device__ __half g_Bu_h[L * 512];           // [l][0:256]=re, [256:512]=im (half)
__device__ unsigned g_xs_h[L * 256];         // half: [l][0:256]=xr, [256:512]=xi
__device__ float g_Mre[NC * P], g_Mim[NC * P];
__device__ float g_bre[NC * P], g_bim[NC * P];
__device__ float g_x0re[NC * P], g_x0im[NC * P];

// ---------------- helpers -----------------------------------------------------
__device__ __forceinline__ unsigned packh2(float a, float b) {
    __half2 h = __floats2half2_rn(a, b);
    return *reinterpret_cast<unsigned*>(&h);
}

__device__ __forceinline__ uint32_t s2u(const void* p) {
    uint32_t a;
    asm("{ .reg .u64 t; cvta.to.shared.u64 t, %1; cvt.u32.u64 %0, t; }" : "=r"(a) : "l"(p));
    return a;
}

__device__ __forceinline__ void mma_f16(float d[4], const unsigned a[4], const unsigned b[2]) {
    asm volatile(
        "mma.sync.aligned.m16n8k16.row.col.f32.f16.f16.f32 "
        "{%0,%1,%2,%3},{%4,%5,%6,%7},{%8,%9},{%0,%1,%2,%3};"
        : "+f"(d[0]), "+f"(d[1]), "+f"(d[2]), "+f"(d[3])
        : "r"(a[0]), "r"(a[1]), "r"(a[2]), "r"(a[3]), "r"(b[0]), "r"(b[1]));
}

__device__ __forceinline__ void ldsm_x4(unsigned r[4], uint32_t addr) {
    asm volatile("ldmatrix.sync.aligned.m8n8.x4.shared.b16 {%0,%1,%2,%3}, [%4];"
        : "=r"(r[0]), "=r"(r[1]), "=r"(r[2]), "=r"(r[3]) : "r"(addr));
}

#define CP16(s, g) \
    asm volatile("cp.async.cg.shared.global [%0], [%1], 16;" :: "r"(s), "l"(g) : "memory")
#define CP_COMMIT() asm volatile("cp.async.commit_group;" ::: "memory")
#define CP_WAIT1() asm volatile("cp.async.wait_group 1;" ::: "memory")
#define CP_WAIT0() asm volatile("cp.async.wait_group 0;" ::: "memory")

// ---------------- setup: Lambda_bar, B_cat (half2), C_cat (half2) ------------
__global__ void k_setup(const float* __restrict__ Lre, const float* __restrict__ Lim,
                        const float* __restrict__ Bin, const float* __restrict__ logstep) {
    int p = blockIdx.x;
    int h2 = threadIdx.x;                 // 0..127 -> pair (2*h2, 2*h2+1)
    float lr = Lre[p], li = Lim[p];
    float dt = expf(logstep[p]);
    float e = expf(lr * dt);
    float Abr = e * cosf(li * dt);
    float Abi = e * sinf(li * dt);
    if (h2 == 0) { g_Are[p] = Abr; g_Aim[p] = Abi; }
    float nr = Abr - 1.0f, ni = Abi;
    float inv = 1.0f / (lr * lr + li * li);
    float cr = (nr * lr + ni * li) * inv;
    float ci = (ni * lr - nr * li) * inv;
    int h0 = 2 * h2;
    float b00 = Bin[(p * H + h0) * 2 + 0], b01 = Bin[(p * H + h0) * 2 + 1];
    float b10 = Bin[(p * H + h0 + 1) * 2 + 0], b11 = Bin[(p * H + h0 + 1) * 2 + 1];
    float re0 = cr * b00 - ci * b01, im0 = cr * b01 + ci * b00;
    float re1 = cr * b10 - ci * b11, im1 = cr * b11 + ci * b10;
    g_Bcat[p * (H / 2) + h2]       = packh2(re0, re1);
    g_Bcat[(P + p) * (H / 2) + h2] = packh2(im0, im1);
}

__global__ void k_deint_C(const float* __restrict__ Cin) {
    int i = blockIdx.x * blockDim.x + threadIdx.x;   // (h, p-pair)
    if (i < H * P / 2) {
        int h = i >> 7, pp = i & 127;
        float4 v = ((const float4*)Cin)[i];
        g_Ccat[h * 256 + pp]       = packh2(v.x, v.z);
        g_Ccat[h * 256 + 128 + pp] = packh2(-v.y, -v.w);
    }
}

__global__ void k_conv_u(const float* __restrict__ u) {
    int i = blockIdx.x * blockDim.x + threadIdx.x;
    if (i < L * H / 2) {
        float2 v = ((const float2*)u)[i];
        g_u_h[i] = packh2(v.x, v.y);
    }
}

// ---------------- unified fp16 GEMM: tile M=128, N=128, 3-stage cp.async ring -
// A row-major [m][KH2 uints], B row-major [n][KH2 uints], NT product.
// 8 warps as 2 (M) x 4 (N); warp tile 64 x 32. ONE __syncthreads per K-step.
template<int KH2, bool EPI_Y>
__global__ __launch_bounds__(256, 2) void k_gemm(const unsigned* __restrict__ Ag,
                                                 const unsigned* __restrict__ Bg,
                                                 void* __restrict__ Cout, int ldc,
                                                 const float* __restrict__ u,
                                                 const float* __restrict__ Dv) {
    constexpr int KITER = KH2 / 16;
    extern __shared__ unsigned sm[];
    const uint32_t sb = s2u(sm);
    const int tid = threadIdx.x, lane = tid & 31, wid = tid >> 5;
    const int bm = blockIdx.x * 128, bn = blockIdx.y * 128;
    const int wr = (wid & 1) * 64, wc = (wid >> 1) * 32;

    const int lr0 = tid >> 2, lc = (tid & 3) * 4;
    const unsigned* gA0 = Ag + (size_t)(bm + lr0) * KH2 + lc;
    const unsigned* gA1 = gA0 + (size_t)64 * KH2;
    const unsigned* gB0 = Bg + (size_t)(bn + lr0) * KH2 + lc;
    const unsigned* gB1 = gB0 + (size_t)64 * KH2;
    const uint32_t dA0 = sb + (lr0 * SST + lc) * 4;
    const uint32_t dA1 = sb + ((lr0 + 64) * SST + lc) * 4;
    const uint32_t dB0 = sb + ((128 + lr0) * SST + lc) * 4;
    const uint32_t dB1 = sb + ((192 + lr0) * SST + lc) * 4;

    // ldmatrix per-thread base offsets (bytes)
    const uint32_t aoff = ((wr + (lane & 15)) * SST + ((lane >> 4) << 2)) * 4;
    const int lg = lane >> 3;
    const uint32_t boff = ((128 + wc + (lg & 2) * 4 + (lane & 7)) * SST + ((lg & 1) << 2)) * 4;

    float acc[4][4][4] = {};

#define PF(c) do { int k0 = (c) * 16; uint32_t bo = ((c) % NSTAGE) * (STG * 4); \
        CP16(dA0 + bo, gA0 + k0); CP16(dA1 + bo, gA1 + k0); \
        CP16(dB0 + bo, gB0 + k0); CP16(dB1 + bo, gB1 + k0); \
        CP_COMMIT(); } while (0)

    PF(0);
    PF(1);
#pragma unroll 1
    for (int c = 0; c < KITER; c++) {
        if (c == KITER - 1) { CP_WAIT0(); } else { CP_WAIT1(); }
        __syncthreads();
        if (c + NSTAGE - 1 < KITER) PF(c + NSTAGE - 1);
        const uint32_t Sb = sb + (c % NSTAGE) * (STG * 4);
#pragma unroll
        for (int ko = 0; ko < 16; ko += 8) {
            unsigned af[4][4];
#pragma unroll
            for (int mt = 0; mt < 4; mt++)
                ldsm_x4(af[mt], Sb + aoff + (mt * 16 * SST + ko) * 4);
#pragma unroll
            for (int nt2 = 0; nt2 < 2; nt2++) {
                unsigned bf[4];
                ldsm_x4(bf, Sb + boff + (nt2 * 16 * SST + ko) * 4);
#pragma unroll
                for (int mt = 0; mt < 4; mt++) {
                    mma_f16(acc[mt][2 * nt2],     af[mt], bf);
                    mma_f16(acc[mt][2 * nt2 + 1], af[mt], bf + 2);
                }
            }
        }
    }
#undef PF

    const int gp = lane >> 2, tg = lane & 3;
#pragma unroll
    for (int mt = 0; mt < 4; mt++)
#pragma unroll
        for (int nt = 0; nt < 4; nt++) {
            int row = bm + wr + mt * 16 + gp;
            int col = bn + wc + nt * 8 + 2 * tg;
            if (EPI_Y) {
                float* outf = (float*)Cout;
                float2 dv = *(const float2*)&Dv[col];
                float2 u0 = *(const float2*)&u[(size_t)row * H + col];
                float2 u1 = *(const float2*)&u[(size_t)(row + 8) * H + col];
                float2 o0 = make_float2(2.0f * acc[mt][nt][0] + u0.x * dv.x,
                                        2.0f * acc[mt][nt][1] + u0.y * dv.y);
                float2 o1 = make_float2(2.0f * acc[mt][nt][2] + u1.x * dv.x,
                                        2.0f * acc[mt][nt][3] + u1.y * dv.y);
                *(float2*)&outf[(size_t)row * ldc + col]       = o0;
                *(float2*)&outf[(size_t)(row + 8) * ldc + col] = o1;
            } else {
                __half* outh = (__half*)Cout;
                *(__half2*)&outh[(size_t)row * ldc + col] =
                    __floats2half2_rn(acc[mt][nt][0], acc[mt][nt][1]);
                *(__half2*)&outh[(size_t)(row + 8) * ldc + col] =
                    __floats2half2_rn(acc[mt][nt][2], acc[mt][nt][3]);
            }
        }
}

// ---------------- scan phase 1: per-chunk affine aggregates ------------------
__global__ __launch_bounds__(256) void k_scan1(const unsigned int* __restrict__ start) {
    int c = blockIdx.x, p = threadIdx.x;
    int l0 = c * CHUNK;
    float Ar = g_Are[p], Ai = g_Aim[p];
    float Mr = 1.0f, Mi = 0.0f, xr = 0.0f, xi = 0.0f;
#pragma unroll 8
    for (int t = 0; t < CHUNK; t++) {
        int l = l0 + t;
        float br = __half2float(g_Bu_h[(size_t)l * 512 + p]);
        float bi = __half2float(g_Bu_h[(size_t)l * 512 + 256 + p]);
        bool s = (start[l] != 0u);
        float pr = s ? 0.0f : xr, pi = s ? 0.0f : xi;
        float mr = s ? 0.0f : Mr, mi = s ? 0.0f : Mi;
        xr = Ar * pr - Ai * pi + br;
        xi = Ar * pi + Ai * pr + bi;
        Mr = Ar * mr - Ai * mi;
        Mi = Ar * mi + Ai * mr;
    }
    g_Mre[c * P + p] = Mr; g_Mim[c * P + p] = Mi;
    g_bre[c * P + p] = xr; g_bim[c * P + p] = xi;
}

// ---------------- scan phase 2: parallel combine over NC chunks --------------
__global__ __launch_bounds__(256) void k_scan2(const float* __restrict__ hidden) {
    __shared__ float sMr[8][32], sMi[8][32], sbr[8][32], sbi[8][32];
    int lane = threadIdx.x & 31, w = threadIdx.x >> 5;
    int p = blockIdx.x * 32 + lane;
    int c0 = w * (NC / 8);

    float Mr = 1.0f, Mi = 0.0f, br = 0.0f, bi = 0.0f;
    for (int j = 0; j < NC / 8; j++) {
        int c = c0 + j;
        float mr = g_Mre[c * P + p], mi = g_Mim[c * P + p];
        float vr = g_bre[c * P + p], vi = g_bim[c * P + p];
        float nMr = mr * Mr - mi * Mi;
        float nMi = mr * Mi + mi * Mr;
        float nbr = mr * br - mi * bi + vr;
        float nbi = mr * bi + mi * br + vi;
        Mr = nMr; Mi = nMi; br = nbr; bi = nbi;
    }
    sMr[w][lane] = Mr; sMi[w][lane] = Mi; sbr[w][lane] = br; sbi[w][lane] = bi;
    __syncthreads();

    if (w == 0) {
        float er = 1.0f, ei = 0.0f, fr = 0.0f, fi = 0.0f;
        for (int ww = 0; ww < 8; ww++) {
            float tMr = sMr[ww][lane], tMi = sMi[ww][lane];
            float tbr = sbr[ww][lane], tbi = sbi[ww][lane];
            sMr[ww][lane] = er; sMi[ww][lane] = ei;
            sbr[ww][lane] = fr; sbi[ww][lane] = fi;
            float ner = tMr * er - tMi * ei;
            float nei = tMr * ei + tMi * er;
            float nfr = tMr * fr - tMi * fi + tbr;
            float nfi = tMr * fi + tMi * fr + tbi;
            er = ner; ei = nei; fr = nfr; fi = nfi;
        }
    }
    __syncthreads();

    float er = sMr[w][lane], ei = sMi[w][lane];
    float fr = sbr[w][lane], fi = sbi[w][lane];
    float x0r = hidden[p], x0i = 0.0f;
    float xr = er * x0r - ei * x0i + fr;
    float xi = er * x0i + ei * x0r + fi;
    for (int j = 0; j < NC / 8; j++) {
        int c = c0 + j;
        g_x0re[c * P + p] = xr;
        g_x0im[c * P + p] = xi;
        float mr = g_Mre[c * P + p], mi = g_Mim[c * P + p];
        float vr = g_bre[c * P + p], vi = g_bim[c * P + p];
        float nr = mr * xr - mi * xi + vr;
        float ni = mr * xi + mi * xr + vi;
        xr = nr; xi = ni;
    }
}

// ---------------- scan phase 3: re-scan, write xs (half) + final state -------
__global__ __launch_bounds__(256) void k_scan3(const unsigned int* __restrict__ start,
                                               float* __restrict__ out, int fmt) {
    int c = blockIdx.x, p = threadIdx.x;
    float Ar = g_Are[p], Ai = g_Aim[p];
    float xr = g_x0re[c * P + p], xi = g_x0im[c * P + p];
    int l0 = c * CHUNK;
    __half* xs = (__half*)g_xs_h;
#pragma unroll 8
    for (int t = 0; t < CHUNK; t++) {
        int l = l0 + t;
        float br = __half2float(g_Bu_h[(size_t)l * 512 + p]);
        float bi = __half2float(g_Bu_h[(size_t)l * 512 + 256 + p]);
        bool s = (start[l] != 0u);
        float pr = s ? 0.0f : xr, pi = s ? 0.0f : xi;
        xr = Ar * pr - Ai * pi + br;
        xi = Ar * pi + Ai * pr + bi;
        xs[(size_t)l * 512 + p]       = __float2half_rn(xr);
        xs[(size_t)l * 512 + 256 + p] = __float2half_rn(xi);
    }
    if (c == NC - 1) {
        if (fmt == 2) { out[2 * p] = xr; out[2 * p + 1] = xi; }
        else if (fmt == 1) { out[p] = xr; }
    }
}

// ---------------- launcher ---------------------------------------------------
extern "C" void kernel_launch(void* const* d_in, const int* in_sizes, int n_in,
                              void* d_out, int out_size) {
    const float* Lre    = (const float*)d_in[0];
    const float* Lim    = (const float*)d_in[1];
    const float* Bin    = (const float*)d_in[2];
    const float* Cin    = (const float*)d_in[3];
    const float* lstep  = (const float*)d_in[4];
    const float* D      = (const float*)d_in[5];
    const float* hidden = (const float*)d_in[6];
    const float* u      = (const float*)d_in[7];
    const unsigned int* start = (const unsigned int*)d_in[8];
    float* out = (float*)d_out;

    int state_floats = out_size - L * H;
    if (state_floats < 0) state_floats = 0;
    int fmt = (state_floats >= 2 * P) ? 2 : (state_floats >= P ? 1 : 0);
    float* ys = out + state_floats;

    cudaFuncSetAttribute(k_gemm<128, false>, cudaFuncAttributeMaxDynamicSharedMemorySize, GSMEM);
    cudaFuncSetAttribute(k_gemm<256, true>,  cudaFuncAttributeMaxDynamicSharedMemorySize, GSMEM);

    k_setup<<<P, H / 2>>>(Lre, Lim, Bin, lstep);
    k_deint_C<<<(H * P / 2 + 255) / 256, 256>>>(Cin);
    k_conv_u<<<(L * H / 2 + 255) / 256, 256>>>(u);

    // GEMM1: Bu_h[l, 0:512] = u @ [Bre; Bim]^T   (K = 256 halves = 128 uints)
    {
        void *bu_dev = nullptr, *a_dev = nullptr, *b_dev = nullptr;
        cudaGetSymbolAddress(&bu_dev, g_Bu_h);
        cudaGetSymbolAddress(&a_dev, g_u_h);
        cudaGetSymbolAddress(&b_dev, g_Bcat);
        dim3 g(L / 128, 512 / 128);
        k_gemm<128, false><<<g, 256, GSMEM>>>((const unsigned*)a_dev, (const unsigned*)b_dev,
                                              bu_dev, 512, nullptr, nullptr);
    }

    k_scan1<<<NC, P>>>(start);
    k_scan2<<<8, 256>>>(hidden);
    k_scan3<<<NC, P>>>(start, out, fmt);

    // GEMM2: ys = 2 * (xs_cat @ Ccat^T) + u * D   (K = 512 halves = 256 uints)
    {
        void *a_dev = nullptr, *b_dev = nullptr;
        cudaGetSymbolAddress(&a_dev, g_xs_h);
        cudaGetSymbolAddress(&b_dev, g_Ccat);
        dim3 g(L / 128, H / 128);
        k_gemm<256, true><<<g, 256, GSMEM>>>((const unsigned*)a_dev, (const unsigned*)b_dev,
                                             ys, H, u, D);
    }
}